// round 10
// baseline (speedup 1.0000x reference)
#include <cuda_runtime.h>
#include <cuda_fp16.h>
#include <cstdint>
#include <math.h>

#define TT 512
#define BB 128
#define II 256
#define HH 1024
#define G4 (4 * HH)
#define K2 2048               // W: [hi(1024) | lo(1024)] fp16
#define NBLK 32               // gate-cols per block (8 hcols)
#define GRIDN 128
#define NTHR 512              // 16 warps: 4(M) x 4(KS)
#define KCH 64
#define NCH (HH / KCH)        // 16
#define STRW_B 4112
#define STRA_B 144
#define W_BYTES (NBLK * STRW_B)          // 131584
#define GRP_B (32 * STRA_B)              // 4608
#define STG_B (4 * GRP_B)                // 18432
#define XP_OFF (W_BYTES + 4 * STG_B)     // 205312
#define C_OFF (XP_OFF + 4 * 4608)        // 223744
#define SMEM_TOTAL (C_OFF + 4096)        // 227840

// ---------------- scratch ---------------------------------------------------
__device__ float g_xproj[(size_t)TT * BB * G4];
__device__ __half g_h[2][BB * HH];
__device__ __half g_Wsplit[(size_t)G4 * K2];
__device__ unsigned g_flag[TT * 64];     // [t][chunk 0..15][mgrp 0..3] -> 8
__device__ unsigned g_ack[TT];           // mainloop-done acks -> 512

// ======================= helpers =============================================
__device__ __forceinline__ uint32_t smem_to_u32(const void* p) {
    uint32_t a;
    asm("{ .reg .u64 t; cvta.to.shared.u64 t, %1; cvt.u32.u64 %0, t; }"
        : "=r"(a) : "l"(p));
    return a;
}
__device__ __forceinline__ void cp_async16(uint32_t dst, const void* src) {
    size_t gsrc = __cvta_generic_to_global(src);
    asm volatile("cp.async.cg.shared.global [%0], [%1], 16;"
                 :: "r"(dst), "l"(gsrc) : "memory");
}
__device__ __forceinline__ void cp_commit() {
    asm volatile("cp.async.commit_group;" ::: "memory");
}
__device__ __forceinline__ void bar_named(int id, int cnt) {
    asm volatile("bar.sync %0, %1;" :: "r"(id), "r"(cnt) : "memory");
}
__device__ __forceinline__ void ldm_x4(uint32_t* r, uint32_t addr) {
    asm volatile("ldmatrix.sync.aligned.m8n8.x4.shared.b16 {%0,%1,%2,%3}, [%4];"
                 : "=r"(r[0]), "=r"(r[1]), "=r"(r[2]), "=r"(r[3]) : "r"(addr));
}
__device__ __forceinline__ void mma_fp16(float* d, const uint32_t* a,
                                         uint32_t b0, uint32_t b1) {
    asm volatile(
        "mma.sync.aligned.m16n8k16.row.col.f32.f16.f16.f32 "
        "{%0,%1,%2,%3}, {%4,%5,%6,%7}, {%8,%9}, {%0,%1,%2,%3};"
        : "+f"(d[0]), "+f"(d[1]), "+f"(d[2]), "+f"(d[3])
        : "r"(a[0]), "r"(a[1]), "r"(a[2]), "r"(a[3]), "r"(b0), "r"(b1));
}
__device__ __forceinline__ unsigned ld_acq(const unsigned* p) {
    unsigned v;
    asm volatile("ld.acquire.gpu.global.u32 %0, [%1];" : "=r"(v) : "l"(p));
    return v;
}
__device__ __forceinline__ void red_relax(unsigned* p) {
    asm volatile("red.relaxed.gpu.global.add.u32 [%0], 1;" :: "l"(p) : "memory");
}
__device__ __forceinline__ void red_rel(unsigned* p) {
    asm volatile("red.release.gpu.global.add.u32 [%0], 1;" :: "l"(p) : "memory");
}
__device__ __forceinline__ float sigf(float x) { return 1.0f / (1.0f + expf(-x)); }

// ======================= init kernels =======================================
__global__ void init_state(const float* __restrict__ h0) {
    int i = blockIdx.x * blockDim.x + threadIdx.x;
    if (i < BB * HH) g_h[0][i] = __float2half(h0[i]);
    if (i < TT * 64) g_flag[i] = 0u;
    if (i < TT) g_ack[i] = 0u;
}

__global__ void wsplit_kernel(const float* __restrict__ W) {
    size_t i = (size_t)blockIdx.x * blockDim.x + threadIdx.x;
    if (i < (size_t)G4 * HH) {
        int n = (int)(i / HH), k = (int)(i % HH);
        float w = W[i];
        __half hi = __float2half(w);
        __half lo = __float2half(w - __half2float(hi));
        int r = ((n & 1023) << 2) | (n >> 10);
        g_Wsplit[(size_t)r * K2 + k] = hi;
        g_Wsplit[(size_t)r * K2 + HH + k] = lo;
    }
}

// ======================= xproj GEMM (fp32, permuted output) =================
__global__ __launch_bounds__(256) void xproj_kernel(
    const float* __restrict__ inp, const float* __restrict__ W_ih,
    const float* __restrict__ b_ih, const float* __restrict__ b_hh)
{
    __shared__ float As[32][64];
    __shared__ float Bs[32][64];
    const int tid = threadIdx.x;
    const int tx = tid & 15, ty = tid >> 4;
    const int n0 = blockIdx.x * 64, m0 = blockIdx.y * 64;

    float acc[4][4];
#pragma unroll
    for (int r = 0; r < 4; r++)
#pragma unroll
        for (int c = 0; c < 4; c++) acc[r][c] = 0.f;

    for (int k0 = 0; k0 < II; k0 += 32) {
#pragma unroll
        for (int v = 0; v < 2; v++) {
            int e = tid + 256 * v;
            int row = e >> 3, kk = (e & 7) * 4;
            float4 a = *(const float4*)(inp + (size_t)(m0 + row) * II + k0 + kk);
            As[kk + 0][row] = a.x; As[kk + 1][row] = a.y;
            As[kk + 2][row] = a.z; As[kk + 3][row] = a.w;
            float4 b = *(const float4*)(W_ih + (size_t)(n0 + row) * II + k0 + kk);
            Bs[kk + 0][row] = b.x; Bs[kk + 1][row] = b.y;
            Bs[kk + 2][row] = b.z; Bs[kk + 3][row] = b.w;
        }
        __syncthreads();
#pragma unroll
        for (int kk = 0; kk < 32; kk++) {
            float4 av = *(const float4*)(&As[kk][ty * 4]);
            float4 bv = *(const float4*)(&Bs[kk][tx * 4]);
            float a4[4] = {av.x, av.y, av.z, av.w};
            float b4[4] = {bv.x, bv.y, bv.z, bv.w};
#pragma unroll
            for (int r = 0; r < 4; r++)
#pragma unroll
                for (int c = 0; c < 4; c++) acc[r][c] += a4[r] * b4[c];
        }
        __syncthreads();
    }
#pragma unroll
    for (int c = 0; c < 4; c++) {
        int n = n0 + tx * 4 + c;
        float bias = b_ih[n] + b_hh[n];
        int pn = ((n & 1023) << 2) | (n >> 10);
#pragma unroll
        for (int r = 0; r < 4; r++) {
            int m = m0 + ty * 4 + r;
            g_xproj[(size_t)m * G4 + pn] = acc[r][c] + bias;
        }
    }
}

// ======================= persistent LSTM, dataflow-synced ===================
__global__ __launch_bounds__(NTHR, 1) void lstm_persistent(
    float* __restrict__ out, const float* __restrict__ c0)
{
    extern __shared__ __align__(16) char smem[];
    const uint32_t sb = smem_to_u32(smem);
    const int tid = threadIdx.x;
    const int wid = tid >> 5, lane = tid & 31;
    const int bidx = blockIdx.x;
    const int n0g = bidx * NBLK;
    const int mgrp = wid & 3;
    const int warp_m = mgrp * 32;
    const int ks = wid >> 2;                 // 0..3
    const int barid = mgrp + 1;
    const int boff = bidx & 15;

    // ---- W slice into smem (once) ----
    for (int i = tid; i < 8192; i += NTHR) {
        int row = i >> 8, gr = i & 255;
        cp_async16(sb + row * STRW_B + gr * 16,
                   g_Wsplit + (size_t)(n0g + row) * K2 + gr * 8);
    }
    cp_commit();
    asm volatile("cp.async.wait_group 0;" ::: "memory");
    // ---- c slice into smem (once) ----
    float* c_s = (float*)(smem + C_OFF);
    for (int i = tid; i < 1024; i += NTHR) {
        int row = i >> 3, hcl = i & 7;
        c_s[i] = c0[(size_t)row * HH + bidx * 8 + hcl];
    }
    __syncthreads();

    const uint32_t stg0 = sb + W_BYTES;
    const size_t OUT_H = (size_t)TT * BB * HH;
    const int q = lane >> 2, r4 = lane & 3;
    const bool writer = (r4 & 1) == 0;
    const int hl = r4 >> 1;
    const int gtid = ks * 32 + lane;         // 0..127 within m-group

    for (int t = 0; t < TT; t++) {
        const int rb = t & 1, wb = rb ^ 1;
        const __half* hbase = g_h[rb];
        const unsigned* fl = g_flag + (size_t)(t - 1) * 64;

        // xproj prefetch for THIS step (ks0 warp owns the buffer)
        if (ks == 0) {
            const float* xs = g_xproj + ((size_t)t * BB + warp_m) * G4 + n0g;
            const uint32_t xd = sb + XP_OFF + mgrp * 4608;
            for (int i = lane; i < 256; i += 32) {
                int row = i >> 3, c16 = i & 7;
                cp_async16(xd + row * 144 + c16 * 16,
                           xs + (size_t)row * G4 + c16 * 4);
            }
        }

        auto issueA = [&](int j, unsigned fv) {
            if (j < NCH) {
                const int jp = (j + boff) & 15;
                if (t > 0) {
                    const unsigned* fp = fl + jp * 4 + mgrp;
                    unsigned v = fv;
                    while (v < 8u) { __nanosleep(64); v = ld_acq(fp); }
                }
                const int k0 = jp * KCH;
                const uint32_t st = stg0 + (j & 3) * STG_B + mgrp * GRP_B;
#pragma unroll
                for (int i2 = 0; i2 < 2; i2++) {
                    int u = gtid * 2 + i2;
                    int row = u >> 3, c16 = u & 7;
                    cp_async16(st + row * STRA_B + c16 * 16,
                               hbase + (size_t)(warp_m + row) * HH + k0 + c16 * 8);
                }
            }
            cp_commit();
        };
        auto probe = [&](int j) -> unsigned {
            if (t == 0 || j >= NCH) return 8u;
            return __ldcg(fl + ((j + boff) & 15) * 4 + mgrp);
        };

        float acc[2][4][4];
#pragma unroll
        for (int mi = 0; mi < 2; mi++)
#pragma unroll
            for (int nf = 0; nf < 4; nf++)
#pragma unroll
                for (int v = 0; v < 4; v++) acc[mi][nf][v] = 0.f;

        issueA(0, probe(0)); issueA(1, probe(1)); issueA(2, probe(2));
        unsigned fnext = probe(3);

        for (int j = 0; j < NCH; j++) {
            asm volatile("cp.async.wait_group 2;" ::: "memory");
            bar_named(barid, 128);

            const int jp = (j + boff) & 15;
            const uint32_t st = stg0 + (j & 3) * STG_B + mgrp * GRP_B;
            uint32_t a[2][4], bhi[2][4], blo[2][4];
            const uint32_t abase = st + (lane & 15) * STRA_B
                                      + (lane >> 4) * 16 + ks * 32;
            ldm_x4(a[0], abase);
            ldm_x4(a[1], abase + 16 * STRA_B);
            const int kk = jp * KCH + ks * 16;
#pragma unroll
            for (int nh = 0; nh < 2; nh++) {
                const uint32_t baddr = sb + (nh * 16 + (lane & 15)) * STRW_B
                                          + kk * 2 + (lane >> 4) * 16;
                ldm_x4(bhi[nh], baddr);
                ldm_x4(blo[nh], baddr + HH * 2);
            }
            unsigned fcur = fnext;
            fnext = probe(j + 4);
            issueA(j + 3, fcur);

#pragma unroll
            for (int mi = 0; mi < 2; mi++)
#pragma unroll
                for (int nh = 0; nh < 2; nh++)
#pragma unroll
                    for (int sub = 0; sub < 2; sub++) {
                        mma_fp16(acc[mi][nh * 2 + sub], a[mi],
                                 bhi[nh][sub], bhi[nh][sub + 2]);
                        mma_fp16(acc[mi][nh * 2 + sub], a[mi],
                                 blo[nh][sub], blo[nh][sub + 2]);
                    }
        }

        asm volatile("cp.async.wait_group 0;" ::: "memory");
        bar_named(barid, 128);
        if (ks == 3 && lane == 0) red_relax(&g_ack[t]);   // group reads done

        // ---------- KS partials via this group's stage slices --------------
        if (ks > 0) {
            char* rp = smem + W_BYTES + (ks - 1) * STG_B + mgrp * GRP_B;
#pragma unroll
            for (int mi = 0; mi < 2; mi++)
#pragma unroll
                for (int nf = 0; nf < 4; nf++)
                    *(float4*)(rp + (((mi * 4 + nf) * 32 + lane) << 4)) =
                        *(const float4*)acc[mi][nf];
        }
        bar_named(barid, 128);
        if (ks == 0) {
#pragma unroll
            for (int s = 0; s < 3; s++) {
                const char* rp = smem + W_BYTES + s * STG_B + mgrp * GRP_B;
#pragma unroll
                for (int mi = 0; mi < 2; mi++)
#pragma unroll
                    for (int nf = 0; nf < 4; nf++) {
                        float4 v = *(const float4*)
                            (rp + (((mi * 4 + nf) * 32 + lane) << 4));
                        acc[mi][nf][0] += v.x; acc[mi][nf][1] += v.y;
                        acc[mi][nf][2] += v.z; acc[mi][nf][3] += v.w;
                    }
            }
        }
        bar_named(barid, 128);    // partial-read done: stages reusable at t+1

        // ---------- epilogue (ks0 warp of each m-group) ---------------------
        if (ks == 0) {
            if (t >= 1) {
                if (lane == 0) {
                    unsigned v = __ldcg(&g_ack[t - 1]);
                    while (v < 512u) { __nanosleep(128); v = ld_acq(&g_ack[t - 1]); }
                }
                __syncwarp();
            }
            const char* xps = smem + XP_OFF + mgrp * 4608;
            __half* hw = g_h[wb];
#pragma unroll
            for (int mi = 0; mi < 2; mi++)
#pragma unroll
                for (int nf = 0; nf < 4; nf++)
#pragma unroll
                    for (int h = 0; h < 2; h++) {
                        float v0 = acc[mi][nf][2 * h];
                        float v1 = acc[mi][nf][2 * h + 1];
                        float p0 = __shfl_xor_sync(0xffffffffu, v0, 1);
                        float p1 = __shfl_xor_sync(0xffffffffu, v1, 1);
                        if (writer) {
                            int mr = mi * 16 + h * 8 + q;          // 0..31
                            int m = warp_m + mr;
                            int hcl = nf * 2 + hl;
                            int hc = bidx * 8 + hcl;
                            float4 xv = *(const float4*)
                                (xps + mr * 144 + (nf * 8 + hl * 4) * 4);
                            float ig = sigf(v0 + xv.x);
                            float fg = sigf(v1 + xv.y);
                            float gg = tanhf(p0 + xv.z);
                            float og = sigf(p1 + xv.w);
                            int ci = m * 8 + hcl;
                            float cn = fg * c_s[ci] + ig * gg;
                            c_s[ci] = cn;
                            float hn = og * tanhf(cn);
                            size_t oidx = (size_t)m * HH + hc;
                            out[(size_t)t * BB * HH + oidx] = hn;
                            __stcg(&hw[oidx], __float2half(hn));
                            if (t == TT - 1) {
                                out[OUT_H + oidx] = hn;
                                out[OUT_H + (size_t)BB * HH + oidx] = cn;
                            }
                        }
                    }
            __syncwarp();
            if (lane == 0)
                red_rel(&g_flag[(size_t)t * 64 + (bidx >> 3) * 4 + mgrp]);
        }
    }
}

// ============================================================================
extern "C" void kernel_launch(void* const* d_in, const int* in_sizes, int n_in,
                              void* d_out, int out_size) {
    const float* inputs = (const float*)d_in[0];
    const float* h0     = (const float*)d_in[1];
    const float* c0     = (const float*)d_in[2];
    const float* W_ih   = (const float*)d_in[3];
    const float* W_hh   = (const float*)d_in[4];
    const float* b_ih   = (const float*)d_in[5];
    const float* b_hh   = (const float*)d_in[6];
    float* out = (float*)d_out;

    cudaFuncSetAttribute(lstm_persistent,
                         cudaFuncAttributeMaxDynamicSharedMemorySize, SMEM_TOTAL);

    init_state<<<(BB * HH + 255) / 256, 256>>>(h0);
    wsplit_kernel<<<(int)(((size_t)G4 * HH + 255) / 256), 256>>>(W_hh);

    dim3 xgrid(G4 / 64, (TT * BB) / 64);
    xproj_kernel<<<xgrid, 256>>>(inputs, W_ih, b_ih, b_hh);

    lstm_persistent<<<GRIDN, NTHR, SMEM_TOTAL>>>(out, c0);
}

// round 11
// speedup vs baseline: 1.1385x; 1.1385x over previous
#include <cuda_runtime.h>
#include <cuda_fp16.h>
#include <cstdint>
#include <math.h>

#define TT 512
#define BB 128
#define II 256
#define HH 1024
#define G4 (4 * HH)
#define NBLK 32               // gate-cols per block (8 hcols)
#define GRIDN 128
#define NTHR 512              // 16 warps: 4(M) x 4(KS)
#define KCH 128
#define NCH (HH / KCH)        // 8 chunks per step
#define STRW_B 2064           // W smem row stride: 1024 fp16 + 16B pad
#define STRA_B 272            // A smem row stride: 128 fp16 (256B) + 16B pad
#define W_BYTES (NBLK * STRW_B)          // 66048
#define GRP_B (32 * STRA_B)              // 8704
#define STG_B (4 * GRP_B)                // 34816
#define NSTAGE 4
#define XP_OFF (W_BYTES + NSTAGE * STG_B)   // 205312
#define C_OFF (XP_OFF + 4 * 4608)           // 223744
#define SMEM_TOTAL (C_OFF + 4096)           // 227840

// ---------------- scratch ---------------------------------------------------
__device__ float g_xproj[(size_t)TT * BB * G4];
__device__ __half g_h[2][BB * HH];
__device__ __half g_W16[(size_t)G4 * HH];    // fp16 W, gate-interleaved rows
__device__ unsigned g_flag[TT * 32];         // [t][chunk 0..7][mgrp] -> 16
__device__ unsigned g_ack[TT];               // mainloop-done acks -> 512

// ======================= helpers =============================================
__device__ __forceinline__ uint32_t smem_to_u32(const void* p) {
    uint32_t a;
    asm("{ .reg .u64 t; cvta.to.shared.u64 t, %1; cvt.u32.u64 %0, t; }"
        : "=r"(a) : "l"(p));
    return a;
}
__device__ __forceinline__ void cp_async16(uint32_t dst, const void* src) {
    size_t gsrc = __cvta_generic_to_global(src);
    asm volatile("cp.async.cg.shared.global [%0], [%1], 16;"
                 :: "r"(dst), "l"(gsrc) : "memory");
}
__device__ __forceinline__ void cp_commit() {
    asm volatile("cp.async.commit_group;" ::: "memory");
}
__device__ __forceinline__ void bar_named(int id, int cnt) {
    asm volatile("bar.sync %0, %1;" :: "r"(id), "r"(cnt) : "memory");
}
__device__ __forceinline__ void ldm_x4(uint32_t* r, uint32_t addr) {
    asm volatile("ldmatrix.sync.aligned.m8n8.x4.shared.b16 {%0,%1,%2,%3}, [%4];"
                 : "=r"(r[0]), "=r"(r[1]), "=r"(r[2]), "=r"(r[3]) : "r"(addr));
}
__device__ __forceinline__ void mma_fp16(float* d, const uint32_t* a,
                                         uint32_t b0, uint32_t b1) {
    asm volatile(
        "mma.sync.aligned.m16n8k16.row.col.f32.f16.f16.f32 "
        "{%0,%1,%2,%3}, {%4,%5,%6,%7}, {%8,%9}, {%0,%1,%2,%3};"
        : "+f"(d[0]), "+f"(d[1]), "+f"(d[2]), "+f"(d[3])
        : "r"(a[0]), "r"(a[1]), "r"(a[2]), "r"(a[3]), "r"(b0), "r"(b1));
}
__device__ __forceinline__ unsigned ld_acq(const unsigned* p) {
    unsigned v;
    asm volatile("ld.acquire.gpu.global.u32 %0, [%1];" : "=r"(v) : "l"(p));
    return v;
}
__device__ __forceinline__ void red_relax(unsigned* p) {
    asm volatile("red.relaxed.gpu.global.add.u32 [%0], 1;" :: "l"(p) : "memory");
}
__device__ __forceinline__ void red_rel(unsigned* p) {
    asm volatile("red.release.gpu.global.add.u32 [%0], 1;" :: "l"(p) : "memory");
}
__device__ __forceinline__ float sigf(float x) { return 1.0f / (1.0f + expf(-x)); }

// ======================= init kernels =======================================
__global__ void init_state(const float* __restrict__ h0) {
    int i = blockIdx.x * blockDim.x + threadIdx.x;
    if (i < BB * HH) g_h[0][i] = __float2half(h0[i]);
    if (i < TT * 32) g_flag[i] = 0u;
    if (i < TT) g_ack[i] = 0u;
}

__global__ void wsplit_kernel(const float* __restrict__ W) {
    size_t i = (size_t)blockIdx.x * blockDim.x + threadIdx.x;
    if (i < (size_t)G4 * HH) {
        int n = (int)(i / HH), k = (int)(i % HH);
        int r = ((n & 1023) << 2) | (n >> 10);   // gate-interleaved perm
        g_W16[(size_t)r * HH + k] = __float2half(W[i]);
    }
}

// ======================= xproj GEMM (fp32, permuted output) =================
__global__ __launch_bounds__(256) void xproj_kernel(
    const float* __restrict__ inp, const float* __restrict__ W_ih,
    const float* __restrict__ b_ih, const float* __restrict__ b_hh)
{
    __shared__ float As[32][64];
    __shared__ float Bs[32][64];
    const int tid = threadIdx.x;
    const int tx = tid & 15, ty = tid >> 4;
    const int n0 = blockIdx.x * 64, m0 = blockIdx.y * 64;

    float acc[4][4];
#pragma unroll
    for (int r = 0; r < 4; r++)
#pragma unroll
        for (int c = 0; c < 4; c++) acc[r][c] = 0.f;

    for (int k0 = 0; k0 < II; k0 += 32) {
#pragma unroll
        for (int v = 0; v < 2; v++) {
            int e = tid + 256 * v;
            int row = e >> 3, kk = (e & 7) * 4;
            float4 a = *(const float4*)(inp + (size_t)(m0 + row) * II + k0 + kk);
            As[kk + 0][row] = a.x; As[kk + 1][row] = a.y;
            As[kk + 2][row] = a.z; As[kk + 3][row] = a.w;
            float4 b = *(const float4*)(W_ih + (size_t)(n0 + row) * II + k0 + kk);
            Bs[kk + 0][row] = b.x; Bs[kk + 1][row] = b.y;
            Bs[kk + 2][row] = b.z; Bs[kk + 3][row] = b.w;
        }
        __syncthreads();
#pragma unroll
        for (int kk = 0; kk < 32; kk++) {
            float4 av = *(const float4*)(&As[kk][ty * 4]);
            float4 bv = *(const float4*)(&Bs[kk][tx * 4]);
            float a4[4] = {av.x, av.y, av.z, av.w};
            float b4[4] = {bv.x, bv.y, bv.z, bv.w};
#pragma unroll
            for (int r = 0; r < 4; r++)
#pragma unroll
                for (int c = 0; c < 4; c++) acc[r][c] += a4[r] * b4[c];
        }
        __syncthreads();
    }
#pragma unroll
    for (int c = 0; c < 4; c++) {
        int n = n0 + tx * 4 + c;
        float bias = b_ih[n] + b_hh[n];
        int pn = ((n & 1023) << 2) | (n >> 10);
#pragma unroll
        for (int r = 0; r < 4; r++) {
            int m = m0 + ty * 4 + r;
            g_xproj[(size_t)m * G4 + pn] = acc[r][c] + bias;
        }
    }
}

// ======================= persistent LSTM, dataflow-synced ===================
__global__ __launch_bounds__(NTHR, 1) void lstm_persistent(
    float* __restrict__ out, const float* __restrict__ c0)
{
    extern __shared__ __align__(16) char smem[];
    const uint32_t sb = smem_to_u32(smem);
    const int tid = threadIdx.x;
    const int wid = tid >> 5, lane = tid & 31;
    const int bidx = blockIdx.x;
    const int n0g = bidx * NBLK;
    const int mgrp = wid & 3;
    const int warp_m = mgrp * 32;
    const int ks = wid >> 2;                 // 0..3 (32 k each)
    const int barid = mgrp + 1;
    const int boff = bidx & 7;

    // ---- W slice (32 rows x 1024 fp16 = 32 x 128 x 16B) into smem, once ----
    for (int i = tid; i < 4096; i += NTHR) {
        int row = i >> 7, gr = i & 127;
        cp_async16(sb + row * STRW_B + gr * 16,
                   g_W16 + (size_t)(n0g + row) * HH + gr * 8);
    }
    cp_commit();
    asm volatile("cp.async.wait_group 0;" ::: "memory");
    // ---- c slice into smem, once ----
    float* c_s = (float*)(smem + C_OFF);
    for (int i = tid; i < 1024; i += NTHR) {
        int row = i >> 3, hcl = i & 7;
        c_s[i] = c0[(size_t)row * HH + bidx * 8 + hcl];
    }
    __syncthreads();

    const uint32_t stg0 = sb + W_BYTES;
    const size_t OUT_H = (size_t)TT * BB * HH;
    const int q = lane >> 2, r4 = lane & 3;
    const bool writer = (r4 & 1) == 0;
    const int hl = r4 >> 1;
    const int gtid = ks * 32 + lane;         // 0..127 within m-group

    for (int t = 0; t < TT; t++) {
        const int rb = t & 1, wb = rb ^ 1;
        const __half* hbase = g_h[rb];
        const unsigned* fl = g_flag + (size_t)(t - 1) * 32;

        // xproj prefetch for THIS step (ks0 warp owns the buffer)
        if (ks == 0) {
            const float* xs = g_xproj + ((size_t)t * BB + warp_m) * G4 + n0g;
            const uint32_t xd = sb + XP_OFF + mgrp * 4608;
            for (int i = lane; i < 256; i += 32) {
                int row = i >> 3, c16 = i & 7;
                cp_async16(xd + row * 144 + c16 * 16,
                           xs + (size_t)row * G4 + c16 * 4);
            }
        }

        auto issueA = [&](int j, unsigned fv) {
            if (j < NCH) {
                const int jp = (j + boff) & 7;
                if (t > 0) {
                    const unsigned* fp = fl + jp * 4 + mgrp;
                    unsigned v = fv;
                    while (v < 16u) { __nanosleep(64); v = ld_acq(fp); }
                }
                const int k0 = jp * KCH;
                const uint32_t st = stg0 + (j & 3) * STG_B + mgrp * GRP_B;
#pragma unroll
                for (int i4 = 0; i4 < 4; i4++) {
                    int u = gtid * 4 + i4;             // 0..511
                    int row = u >> 4, c16 = u & 15;    // 32 rows x 16 groups
                    cp_async16(st + row * STRA_B + c16 * 16,
                               hbase + (size_t)(warp_m + row) * HH + k0 + c16 * 8);
                }
            }
            cp_commit();
        };
        auto probe = [&](int j) -> unsigned {
            if (t == 0 || j >= NCH) return 16u;
            return __ldcg(fl + ((j + boff) & 7) * 4 + mgrp);
        };

        float acc[2][4][4];
#pragma unroll
        for (int mi = 0; mi < 2; mi++)
#pragma unroll
            for (int nf = 0; nf < 4; nf++)
#pragma unroll
                for (int v = 0; v < 4; v++) acc[mi][nf][v] = 0.f;

        issueA(0, probe(0)); issueA(1, probe(1)); issueA(2, probe(2));
        unsigned fnext = probe(3);

        for (int j = 0; j < NCH; j++) {
            asm volatile("cp.async.wait_group 2;" ::: "memory");
            bar_named(barid, 128);

            const int jp = (j + boff) & 7;
            const uint32_t st = stg0 + (j & 3) * STG_B + mgrp * GRP_B;
            uint32_t a[2][2][4], b[2][2][4];
            const uint32_t abase = st + (lane & 15) * STRA_B
                                      + (lane >> 4) * 16 + ks * 64;
#pragma unroll
            for (int u = 0; u < 2; u++) {
                ldm_x4(a[0][u], abase + u * 32);
                ldm_x4(a[1][u], abase + u * 32 + 16 * STRA_B);
            }
#pragma unroll
            for (int u = 0; u < 2; u++) {
                const int kk = jp * KCH + ks * 32 + u * 16;
#pragma unroll
                for (int nh = 0; nh < 2; nh++) {
                    const uint32_t baddr = sb + (nh * 16 + (lane & 15)) * STRW_B
                                              + kk * 2 + (lane >> 4) * 16;
                    ldm_x4(b[u][nh], baddr);
                }
            }
            unsigned fcur = fnext;
            fnext = probe(j + 4);
            issueA(j + 3, fcur);

#pragma unroll
            for (int u = 0; u < 2; u++)
#pragma unroll
                for (int mi = 0; mi < 2; mi++)
#pragma unroll
                    for (int nh = 0; nh < 2; nh++)
#pragma unroll
                        for (int sub = 0; sub < 2; sub++)
                            mma_fp16(acc[mi][nh * 2 + sub], a[mi][u],
                                     b[u][nh][sub], b[u][nh][sub + 2]);
        }

        asm volatile("cp.async.wait_group 0;" ::: "memory");
        bar_named(barid, 128);
        if (ks == 3 && lane == 0) red_relax(&g_ack[t]);   // group reads done

        // ---------- KS partials via this group's stage slices --------------
        if (ks > 0) {
            char* rp = smem + W_BYTES + (ks - 1) * STG_B + mgrp * GRP_B;
#pragma unroll
            for (int mi = 0; mi < 2; mi++)
#pragma unroll
                for (int nf = 0; nf < 4; nf++)
                    *(float4*)(rp + (((mi * 4 + nf) * 32 + lane) << 4)) =
                        *(const float4*)acc[mi][nf];
        }
        bar_named(barid, 128);
        if (ks == 0) {
#pragma unroll
            for (int s = 0; s < 3; s++) {
                const char* rp = smem + W_BYTES + s * STG_B + mgrp * GRP_B;
#pragma unroll
                for (int mi = 0; mi < 2; mi++)
#pragma unroll
                    for (int nf = 0; nf < 4; nf++) {
                        float4 v = *(const float4*)
                            (rp + (((mi * 4 + nf) * 32 + lane) << 4));
                        acc[mi][nf][0] += v.x; acc[mi][nf][1] += v.y;
                        acc[mi][nf][2] += v.z; acc[mi][nf][3] += v.w;
                    }
            }
        }
        bar_named(barid, 128);    // partial-read done: stages reusable at t+1

        // ---------- epilogue (ks0 warp of each m-group) ---------------------
        if (ks == 0) {
            if (t >= 1) {
                if (lane == 0) {
                    unsigned v = __ldcg(&g_ack[t - 1]);
                    while (v < 512u) { __nanosleep(128); v = ld_acq(&g_ack[t - 1]); }
                }
                __syncwarp();
            }
            const char* xps = smem + XP_OFF + mgrp * 4608;
            __half* hw = g_h[wb];
#pragma unroll
            for (int mi = 0; mi < 2; mi++)
#pragma unroll
                for (int nf = 0; nf < 4; nf++)
#pragma unroll
                    for (int h = 0; h < 2; h++) {
                        float v0 = acc[mi][nf][2 * h];
                        float v1 = acc[mi][nf][2 * h + 1];
                        float p0 = __shfl_xor_sync(0xffffffffu, v0, 1);
                        float p1 = __shfl_xor_sync(0xffffffffu, v1, 1);
                        if (writer) {
                            int mr = mi * 16 + h * 8 + q;          // 0..31
                            int m = warp_m + mr;
                            int hcl = nf * 2 + hl;
                            int hc = bidx * 8 + hcl;
                            float4 xv = *(const float4*)
                                (xps + mr * 144 + (nf * 8 + hl * 4) * 4);
                            float ig = sigf(v0 + xv.x);
                            float fg = sigf(v1 + xv.y);
                            float gg = tanhf(p0 + xv.z);
                            float og = sigf(p1 + xv.w);
                            int ci = m * 8 + hcl;
                            float cn = fg * c_s[ci] + ig * gg;
                            c_s[ci] = cn;
                            float hn = og * tanhf(cn);
                            size_t oidx = (size_t)m * HH + hc;
                            out[(size_t)t * BB * HH + oidx] = hn;
                            __stcg(&hw[oidx], __float2half(hn));
                            if (t == TT - 1) {
                                out[OUT_H + oidx] = hn;
                                out[OUT_H + (size_t)BB * HH + oidx] = cn;
                            }
                        }
                    }
            __syncwarp();
            if (lane == 0)
                red_rel(&g_flag[(size_t)t * 32 + (bidx >> 4) * 4 + mgrp]);
        }
    }
}

// ============================================================================
extern "C" void kernel_launch(void* const* d_in, const int* in_sizes, int n_in,
                              void* d_out, int out_size) {
    const float* inputs = (const float*)d_in[0];
    const float* h0     = (const float*)d_in[1];
    const float* c0     = (const float*)d_in[2];
    const float* W_ih   = (const float*)d_in[3];
    const float* W_hh   = (const float*)d_in[4];
    const float* b_ih   = (const float*)d_in[5];
    const float* b_hh   = (const float*)d_in[6];
    float* out = (float*)d_out;

    cudaFuncSetAttribute(lstm_persistent,
                         cudaFuncAttributeMaxDynamicSharedMemorySize, SMEM_TOTAL);

    init_state<<<(BB * HH + 255) / 256, 256>>>(h0);
    wsplit_kernel<<<(int)(((size_t)G4 * HH + 255) / 256), 256>>>(W_hh);

    dim3 xgrid(G4 / 64, (TT * BB) / 64);
    xproj_kernel<<<xgrid, 256>>>(inputs, W_ih, b_ih, b_hh);

    lstm_persistent<<<GRIDN, NTHR, SMEM_TOTAL>>>(out, c0);
}

// round 12
// speedup vs baseline: 1.2161x; 1.0681x over previous
#include <cuda_runtime.h>
#include <cuda_fp16.h>
#include <cstdint>
#include <math.h>

#define TT 512
#define BB 128
#define II 256
#define HH 1024
#define G4 (4 * HH)
#define NBLK 32               // gate-cols per block (8 hcols)
#define GRIDN 128
#define NTHR 512              // 16 warps: 4(M) x 4(KS)
#define KCH 128
#define NCH (HH / KCH)        // 8 chunks per step
#define STRW_B 2064           // W smem row stride: 1024 fp16 + 16B pad
#define STRA_B 272            // A smem row stride: 128 fp16 (256B) + 16B pad
#define W_BYTES (NBLK * STRW_B)          // 66048
#define GRP_B (32 * STRA_B)              // 8704
#define STG_B (4 * GRP_B)                // 34816
#define NSTAGE 4
#define XP_OFF (W_BYTES + NSTAGE * STG_B)   // 205312
#define C_OFF (XP_OFF + 4 * 4608)           // 223744
#define SMEM_TOTAL (C_OFF + 4096)           // 227840

// ---------------- scratch ---------------------------------------------------
__device__ float g_xproj[(size_t)TT * BB * G4];
__device__ __half g_h[2][BB * HH];
__device__ __half g_W16[(size_t)G4 * HH];    // fp16 W, gate-interleaved rows
__device__ unsigned g_flag[TT * 32];         // [t][chunk 0..7][mgrp] -> 16
__device__ unsigned g_ack[TT];               // mainloop-done acks -> 512

// ======================= helpers =============================================
__device__ __forceinline__ uint32_t smem_to_u32(const void* p) {
    uint32_t a;
    asm("{ .reg .u64 t; cvta.to.shared.u64 t, %1; cvt.u32.u64 %0, t; }"
        : "=r"(a) : "l"(p));
    return a;
}
__device__ __forceinline__ void cp_async16(uint32_t dst, const void* src) {
    size_t gsrc = __cvta_generic_to_global(src);
    asm volatile("cp.async.cg.shared.global [%0], [%1], 16;"
                 :: "r"(dst), "l"(gsrc) : "memory");
}
__device__ __forceinline__ void cp_commit() {
    asm volatile("cp.async.commit_group;" ::: "memory");
}
__device__ __forceinline__ void bar_named(int id, int cnt) {
    asm volatile("bar.sync %0, %1;" :: "r"(id), "r"(cnt) : "memory");
}
__device__ __forceinline__ void ldm_x4(uint32_t* r, uint32_t addr) {
    asm volatile("ldmatrix.sync.aligned.m8n8.x4.shared.b16 {%0,%1,%2,%3}, [%4];"
                 : "=r"(r[0]), "=r"(r[1]), "=r"(r[2]), "=r"(r[3]) : "r"(addr));
}
__device__ __forceinline__ void mma_fp16(float* d, const uint32_t* a,
                                         uint32_t b0, uint32_t b1) {
    asm volatile(
        "mma.sync.aligned.m16n8k16.row.col.f32.f16.f16.f32 "
        "{%0,%1,%2,%3}, {%4,%5,%6,%7}, {%8,%9}, {%0,%1,%2,%3};"
        : "+f"(d[0]), "+f"(d[1]), "+f"(d[2]), "+f"(d[3])
        : "r"(a[0]), "r"(a[1]), "r"(a[2]), "r"(a[3]), "r"(b0), "r"(b1));
}
__device__ __forceinline__ unsigned ld_acq(const unsigned* p) {
    unsigned v;
    asm volatile("ld.acquire.gpu.global.u32 %0, [%1];" : "=r"(v) : "l"(p));
    return v;
}
__device__ __forceinline__ void red_rel(unsigned* p) {
    asm volatile("red.release.gpu.global.add.u32 [%0], 1;" :: "l"(p) : "memory");
}
// fast sigmoid/tanh: __expf (MUFU.EX2) + approx divide; clamp avoids inf/NaN
__device__ __forceinline__ float fsig(float x) {
    x = fminf(fmaxf(x, -20.f), 20.f);
    return __fdividef(1.f, 1.f + __expf(-x));
}
__device__ __forceinline__ float ftanh(float x) {
    x = fminf(fmaxf(x, -20.f), 20.f);
    float e = __expf(-2.f * x);
    return __fdividef(1.f - e, 1.f + e);
}

// ======================= init kernels =======================================
__global__ void init_state(const float* __restrict__ h0) {
    int i = blockIdx.x * blockDim.x + threadIdx.x;
    if (i < BB * HH) g_h[0][i] = __float2half(h0[i]);
    if (i < TT * 32) g_flag[i] = 0u;
    if (i < TT) g_ack[i] = 0u;
}

__global__ void wsplit_kernel(const float* __restrict__ W) {
    size_t i = (size_t)blockIdx.x * blockDim.x + threadIdx.x;
    if (i < (size_t)G4 * HH) {
        int n = (int)(i / HH), k = (int)(i % HH);
        int r = ((n & 1023) << 2) | (n >> 10);   // gate-interleaved perm
        g_W16[(size_t)r * HH + k] = __float2half(W[i]);
    }
}

// ======================= xproj GEMM (fp32, permuted output) =================
__global__ __launch_bounds__(256) void xproj_kernel(
    const float* __restrict__ inp, const float* __restrict__ W_ih,
    const float* __restrict__ b_ih, const float* __restrict__ b_hh)
{
    __shared__ float As[32][64];
    __shared__ float Bs[32][64];
    const int tid = threadIdx.x;
    const int tx = tid & 15, ty = tid >> 4;
    const int n0 = blockIdx.x * 64, m0 = blockIdx.y * 64;

    float acc[4][4];
#pragma unroll
    for (int r = 0; r < 4; r++)
#pragma unroll
        for (int c = 0; c < 4; c++) acc[r][c] = 0.f;

    for (int k0 = 0; k0 < II; k0 += 32) {
#pragma unroll
        for (int v = 0; v < 2; v++) {
            int e = tid + 256 * v;
            int row = e >> 3, kk = (e & 7) * 4;
            float4 a = *(const float4*)(inp + (size_t)(m0 + row) * II + k0 + kk);
            As[kk + 0][row] = a.x; As[kk + 1][row] = a.y;
            As[kk + 2][row] = a.z; As[kk + 3][row] = a.w;
            float4 b = *(const float4*)(W_ih + (size_t)(n0 + row) * II + k0 + kk);
            Bs[kk + 0][row] = b.x; Bs[kk + 1][row] = b.y;
            Bs[kk + 2][row] = b.z; Bs[kk + 3][row] = b.w;
        }
        __syncthreads();
#pragma unroll
        for (int kk = 0; kk < 32; kk++) {
            float4 av = *(const float4*)(&As[kk][ty * 4]);
            float4 bv = *(const float4*)(&Bs[kk][tx * 4]);
            float a4[4] = {av.x, av.y, av.z, av.w};
            float b4[4] = {bv.x, bv.y, bv.z, bv.w};
#pragma unroll
            for (int r = 0; r < 4; r++)
#pragma unroll
                for (int c = 0; c < 4; c++) acc[r][c] += a4[r] * b4[c];
        }
        __syncthreads();
    }
#pragma unroll
    for (int c = 0; c < 4; c++) {
        int n = n0 + tx * 4 + c;
        float bias = b_ih[n] + b_hh[n];
        int pn = ((n & 1023) << 2) | (n >> 10);
#pragma unroll
        for (int r = 0; r < 4; r++) {
            int m = m0 + ty * 4 + r;
            g_xproj[(size_t)m * G4 + pn] = acc[r][c] + bias;
        }
    }
}

// ======================= persistent LSTM, dataflow-synced ===================
__global__ __launch_bounds__(NTHR, 1) void lstm_persistent(
    float* __restrict__ out, const float* __restrict__ c0)
{
    extern __shared__ __align__(16) char smem[];
    const uint32_t sb = smem_to_u32(smem);
    const int tid = threadIdx.x;
    const int wid = tid >> 5, lane = tid & 31;
    const int bidx = blockIdx.x;
    const int n0g = bidx * NBLK;
    const int mgrp = wid & 3;
    const int warp_m = mgrp * 32;
    const int ks = wid >> 2;                 // 0..3
    const int barid = mgrp + 1;
    const int boff = bidx & 7;

    for (int i = tid; i < 4096; i += NTHR) {
        int row = i >> 7, gr = i & 127;
        cp_async16(sb + row * STRW_B + gr * 16,
                   g_W16 + (size_t)(n0g + row) * HH + gr * 8);
    }
    cp_commit();
    asm volatile("cp.async.wait_group 0;" ::: "memory");
    float* c_s = (float*)(smem + C_OFF);
    for (int i = tid; i < 1024; i += NTHR) {
        int row = i >> 3, hcl = i & 7;
        c_s[i] = c0[(size_t)row * HH + bidx * 8 + hcl];
    }
    __syncthreads();

    const uint32_t stg0 = sb + W_BYTES;
    const size_t OUT_H = (size_t)TT * BB * HH;
    const int q = lane >> 2, r4 = lane & 3;
    const bool writer = (r4 & 1) == 0;
    const int hl = r4 >> 1;
    const int gtid = ks * 32 + lane;

    for (int t = 0; t < TT; t++) {
        const int rb = t & 1, wb = rb ^ 1;
        const __half* hbase = g_h[rb];
        const unsigned* fl = g_flag + (size_t)(t - 1) * 32;

        if (ks == 0) {
            const float* xs = g_xproj + ((size_t)t * BB + warp_m) * G4 + n0g;
            const uint32_t xd = sb + XP_OFF + mgrp * 4608;
            for (int i = lane; i < 256; i += 32) {
                int row = i >> 3, c16 = i & 7;
                cp_async16(xd + row * 144 + c16 * 16,
                           xs + (size_t)row * G4 + c16 * 4);
            }
        }

        auto issueA = [&](int j, unsigned fv) {
            if (j < NCH) {
                const int jp = (j + boff) & 7;
                if (t > 0) {
                    const unsigned* fp = fl + jp * 4 + mgrp;
                    unsigned v = fv;
                    while (v < 16u) v = ld_acq(fp);
                }
                const int k0 = jp * KCH;
                const uint32_t st = stg0 + (j & 3) * STG_B + mgrp * GRP_B;
#pragma unroll
                for (int i4 = 0; i4 < 4; i4++) {
                    int u = gtid * 4 + i4;
                    int row = u >> 4, c16 = u & 15;
                    cp_async16(st + row * STRA_B + c16 * 16,
                               hbase + (size_t)(warp_m + row) * HH + k0 + c16 * 8);
                }
            }
            cp_commit();
        };
        auto probe = [&](int j) -> unsigned {
            if (t == 0 || j >= NCH) return 16u;
            return __ldcg(fl + ((j + boff) & 7) * 4 + mgrp);
        };

        float acc[2][4][4];
#pragma unroll
        for (int mi = 0; mi < 2; mi++)
#pragma unroll
            for (int nf = 0; nf < 4; nf++)
#pragma unroll
                for (int v = 0; v < 4; v++) acc[mi][nf][v] = 0.f;

        issueA(0, probe(0)); issueA(1, probe(1)); issueA(2, probe(2));
        unsigned fnext = probe(3);

        for (int j = 0; j < NCH; j++) {
            asm volatile("cp.async.wait_group 2;" ::: "memory");
            bar_named(barid, 128);

            const int jp = (j + boff) & 7;
            const uint32_t st = stg0 + (j & 3) * STG_B + mgrp * GRP_B;
            uint32_t a[2][2][4], b[2][2][4];
            const uint32_t abase = st + (lane & 15) * STRA_B
                                      + (lane >> 4) * 16 + ks * 64;
#pragma unroll
            for (int u = 0; u < 2; u++) {
                ldm_x4(a[0][u], abase + u * 32);
                ldm_x4(a[1][u], abase + u * 32 + 16 * STRA_B);
            }
#pragma unroll
            for (int u = 0; u < 2; u++) {
                const int kk = jp * KCH + ks * 32 + u * 16;
#pragma unroll
                for (int nh = 0; nh < 2; nh++) {
                    const uint32_t baddr = sb + (nh * 16 + (lane & 15)) * STRW_B
                                              + kk * 2 + (lane >> 4) * 16;
                    ldm_x4(b[u][nh], baddr);
                }
            }
            unsigned fcur = fnext;
            fnext = probe(j + 4);
            issueA(j + 3, fcur);

#pragma unroll
            for (int u = 0; u < 2; u++)
#pragma unroll
                for (int mi = 0; mi < 2; mi++)
#pragma unroll
                    for (int nh = 0; nh < 2; nh++)
#pragma unroll
                        for (int sub = 0; sub < 2; sub++)
                            mma_fp16(acc[mi][nh * 2 + sub], a[mi][u],
                                     b[u][nh][sub], b[u][nh][sub + 2]);
        }

        asm volatile("cp.async.wait_group 0;" ::: "memory");

        // ---- partial write: warp (mgrp, ks) parks acc in stage ks ----------
        {
            char* pw = smem + W_BYTES + ks * STG_B + mgrp * GRP_B;
#pragma unroll
            for (int mi = 0; mi < 2; mi++)
#pragma unroll
                for (int nf = 0; nf < 4; nf++)
                    *(float4*)(pw + (((mi * 4 + nf) * 32 + lane) << 4)) =
                        *(const float4*)acc[mi][nf];
        }
        bar_named(barid, 128);
        if (ks == 3 && lane == 0) red_rel(&g_ack[t]);   // all reads of rb done

        // ---- all-reduce slice: warp ks sums nf==ks from the other 3 -------
        float s0[2][4];
#pragma unroll
        for (int mi = 0; mi < 2; mi++)
#pragma unroll
            for (int v = 0; v < 4; v++) s0[mi][v] = acc[mi][ks][v];
#pragma unroll
        for (int s = 0; s < 4; s++) {
            if (s == ks) continue;
            const char* pr = smem + W_BYTES + s * STG_B + mgrp * GRP_B;
#pragma unroll
            for (int mi = 0; mi < 2; mi++) {
                float4 v = *(const float4*)
                    (pr + (((mi * 4 + ks) * 32 + lane) << 4));
                s0[mi][0] += v.x; s0[mi][1] += v.y;
                s0[mi][2] += v.z; s0[mi][3] += v.w;
            }
        }

        // ---- parallel epilogue: warp ks handles hcols 2ks, 2ks+1 ----------
        {
            const char* xps = smem + XP_OFF + mgrp * 4608;
            __half* hw = g_h[wb];
            float hnv[2][2], cnv[2][2];
#pragma unroll
            for (int mi = 0; mi < 2; mi++)
#pragma unroll
                for (int h = 0; h < 2; h++) {
                    float v0 = s0[mi][2 * h];
                    float v1 = s0[mi][2 * h + 1];
                    float p0 = __shfl_xor_sync(0xffffffffu, v0, 1);
                    float p1 = __shfl_xor_sync(0xffffffffu, v1, 1);
                    if (writer) {
                        int mr = mi * 16 + h * 8 + q;
                        int m = warp_m + mr;
                        int hcl = ks * 2 + hl;
                        float4 xv = *(const float4*)
                            (xps + mr * 144 + (ks * 8 + hl * 4) * 4);
                        float ig = fsig(v0 + xv.x);
                        float fg = fsig(v1 + xv.y);
                        float gg = ftanh(p0 + xv.z);
                        float og = fsig(p1 + xv.w);
                        int ci = m * 8 + hcl;
                        float cn = fg * c_s[ci] + ig * gg;
                        c_s[ci] = cn;
                        float hn = og * ftanh(cn);
                        cnv[mi][h] = cn; hnv[mi][h] = hn;
                        out[(size_t)t * BB * HH + (size_t)m * HH
                            + bidx * 8 + hcl] = hn;
                    }
                }
            // WAR: wait until every block finished reading buffer wb (t-1)
            if (t >= 1) {
                if (lane == 0) {
                    const unsigned* ap = &g_ack[t - 1];
                    unsigned v = __ldcg(ap);
                    while (v < 512u) v = ld_acq(ap);
                }
                __syncwarp();
            }
#pragma unroll
            for (int mi = 0; mi < 2; mi++)
#pragma unroll
                for (int h = 0; h < 2; h++)
                    if (writer) {
                        int m = warp_m + mi * 16 + h * 8 + q;
                        int hc = bidx * 8 + ks * 2 + hl;
                        size_t oidx = (size_t)m * HH + hc;
                        __stcg(&hw[oidx], __float2half(hnv[mi][h]));
                        if (t == TT - 1) {
                            out[OUT_H + oidx] = hnv[mi][h];
                            out[OUT_H + (size_t)BB * HH + oidx] = cnv[mi][h];
                        }
                    }
        }
        bar_named(barid, 128);   // h stored by all 4 warps; stages reusable
        if (ks == 0 && lane == 0)
            red_rel(&g_flag[(size_t)t * 32 + (bidx >> 4) * 4 + mgrp]);
    }
}

// ============================================================================
extern "C" void kernel_launch(void* const* d_in, const int* in_sizes, int n_in,
                              void* d_out, int out_size) {
    const float* inputs = (const float*)d_in[0];
    const float* h0     = (const float*)d_in[1];
    const float* c0     = (const float*)d_in[2];
    const float* W_ih   = (const float*)d_in[3];
    const float* W_hh   = (const float*)d_in[4];
    const float* b_ih   = (const float*)d_in[5];
    const float* b_hh   = (const float*)d_in[6];
    float* out = (float*)d_out;

    cudaFuncSetAttribute(lstm_persistent,
                         cudaFuncAttributeMaxDynamicSharedMemorySize, SMEM_TOTAL);

    init_state<<<(BB * HH + 255) / 256, 256>>>(h0);
    wsplit_kernel<<<(int)(((size_t)G4 * HH + 255) / 256), 256>>>(W_hh);

    dim3 xgrid(G4 / 64, (TT * BB) / 64);
    xproj_kernel<<<xgrid, 256>>>(inputs, W_ih, b_ih, b_hh);

    lstm_persistent<<<GRIDN, NTHR, SMEM_TOTAL>>>(out, c0);
}

// round 13
// speedup vs baseline: 1.7116x; 1.4075x over previous
#include <cuda_runtime.h>
#include <cuda_fp16.h>
#include <cstdint>
#include <math.h>

#define TT 512
#define BB 128
#define II 256
#define HH 1024
#define G4 (4 * HH)
#define NBLK 32               // gate-cols per block (8 hcols)
#define GRIDN 128
#define NTHR 512              // 16 warps: 4(M) x 4(KS)
#define KCH 128
#define NCH (HH / KCH)        // 8 chunks per step
#define STRW_B 2064           // W smem row stride: 1024 fp16 + 16B pad
#define STRA_B 272            // A smem row stride: 128 fp16 (256B) + 16B pad
#define W_BYTES (NBLK * STRW_B)          // 66048
#define GRP_B (32 * STRA_B)              // 8704
#define STG_B (4 * GRP_B)                // 34816
#define NSTAGE 4
#define XP_OFF (W_BYTES + NSTAGE * STG_B)   // 205312
#define C_OFF (XP_OFF + 4 * 4608)           // 223744
#define SMEM_TOTAL (C_OFF + 4096)           // 227840

// xproj fp16 GEMM tiling
#define XSTR_B 144            // 64 fp16 + 16B pad
#define XA_B (128 * XSTR_B)   // 18432
#define XB_B (64 * XSTR_B)    // 9216
#define XSTG (XA_B + XB_B)    // 27648
#define XSMEM (2 * XSTG)      // 55296

// ---------------- scratch ---------------------------------------------------
__device__ float g_xproj[(size_t)TT * BB * G4];
__device__ __half g_h[2][BB * HH];
__device__ __half g_W16[(size_t)G4 * HH];    // fp16 W_hh, gate-interleaved rows
__device__ __half g_x16[(size_t)TT * BB * II];
__device__ __half g_Wih16[(size_t)G4 * II];  // fp16 W_ih, gate-interleaved rows
__device__ float g_biasp[G4];                // permuted b_ih+b_hh
__device__ unsigned g_flag[TT * 32];         // [t][chunk 0..7][mgrp] -> 16
__device__ unsigned g_ack[TT];               // mainloop-done acks -> 512

// ======================= helpers =============================================
__device__ __forceinline__ uint32_t smem_to_u32(const void* p) {
    uint32_t a;
    asm("{ .reg .u64 t; cvta.to.shared.u64 t, %1; cvt.u32.u64 %0, t; }"
        : "=r"(a) : "l"(p));
    return a;
}
__device__ __forceinline__ void cp_async16(uint32_t dst, const void* src) {
    size_t gsrc = __cvta_generic_to_global(src);
    asm volatile("cp.async.cg.shared.global [%0], [%1], 16;"
                 :: "r"(dst), "l"(gsrc) : "memory");
}
__device__ __forceinline__ void cp_commit() {
    asm volatile("cp.async.commit_group;" ::: "memory");
}
__device__ __forceinline__ void bar_named(int id, int cnt) {
    asm volatile("bar.sync %0, %1;" :: "r"(id), "r"(cnt) : "memory");
}
__device__ __forceinline__ void ldm_x4(uint32_t* r, uint32_t addr) {
    asm volatile("ldmatrix.sync.aligned.m8n8.x4.shared.b16 {%0,%1,%2,%3}, [%4];"
                 : "=r"(r[0]), "=r"(r[1]), "=r"(r[2]), "=r"(r[3]) : "r"(addr));
}
__device__ __forceinline__ void mma_fp16(float* d, const uint32_t* a,
                                         uint32_t b0, uint32_t b1) {
    asm volatile(
        "mma.sync.aligned.m16n8k16.row.col.f32.f16.f16.f32 "
        "{%0,%1,%2,%3}, {%4,%5,%6,%7}, {%8,%9}, {%0,%1,%2,%3};"
        : "+f"(d[0]), "+f"(d[1]), "+f"(d[2]), "+f"(d[3])
        : "r"(a[0]), "r"(a[1]), "r"(a[2]), "r"(a[3]), "r"(b0), "r"(b1));
}
__device__ __forceinline__ unsigned ld_acq(const unsigned* p) {
    unsigned v;
    asm volatile("ld.acquire.gpu.global.u32 %0, [%1];" : "=r"(v) : "l"(p));
    return v;
}
__device__ __forceinline__ void red_rel(unsigned* p) {
    asm volatile("red.release.gpu.global.add.u32 [%0], 1;" :: "l"(p) : "memory");
}
__device__ __forceinline__ float fsig(float x) {
    x = fminf(fmaxf(x, -20.f), 20.f);
    return __fdividef(1.f, 1.f + __expf(-x));
}
__device__ __forceinline__ float ftanh(float x) {
    x = fminf(fmaxf(x, -20.f), 20.f);
    float e = __expf(-2.f * x);
    return __fdividef(1.f - e, 1.f + e);
}

// ======================= init / convert kernels =============================
__global__ void init_state(const float* __restrict__ h0) {
    int i = blockIdx.x * blockDim.x + threadIdx.x;
    if (i < BB * HH) g_h[0][i] = __float2half(h0[i]);
    if (i < TT * 32) g_flag[i] = 0u;
    if (i < TT) g_ack[i] = 0u;
}

__global__ void wsplit_kernel(const float* __restrict__ W) {
    size_t i = (size_t)blockIdx.x * blockDim.x + threadIdx.x;
    if (i < (size_t)G4 * HH) {
        int n = (int)(i / HH), k = (int)(i % HH);
        int r = ((n & 1023) << 2) | (n >> 10);   // gate-interleaved perm
        g_W16[(size_t)r * HH + k] = __float2half(W[i]);
    }
}

__global__ void conv_x16(const float* __restrict__ inp) {
    size_t i = (size_t)blockIdx.x * blockDim.x + threadIdx.x;
    if (i < (size_t)TT * BB * II) g_x16[i] = __float2half(inp[i]);
}

__global__ void conv_wih(const float* __restrict__ W_ih,
                         const float* __restrict__ b_ih,
                         const float* __restrict__ b_hh) {
    int i = blockIdx.x * blockDim.x + threadIdx.x;
    if (i < G4 * II) {
        int n = i >> 8, k = i & 255;
        int r = ((n & 1023) << 2) | (n >> 10);
        g_Wih16[(size_t)r * II + k] = __float2half(W_ih[i]);
        if (k == 0) g_biasp[r] = b_ih[n] + b_hh[n];
    }
}

// ======================= xproj fp16 HMMA GEMM ================================
// C[65536, 4096] = x16[65536,256] @ Wih16[4096,256]^T + biasp (permuted cols)
// grid (64, 512): block = M128 x N64, K=256 in 4 chunks of 64, double-buffered.
// 8 warps: 4(M) x 2(N), warp tile M32 x N32.
__global__ __launch_bounds__(256) void xproj16_kernel() {
    extern __shared__ __align__(16) char smx[];
    const uint32_t sb = smem_to_u32(smx);
    const int tid = threadIdx.x, wid = tid >> 5, lane = tid & 31;
    const int n0 = blockIdx.x * 64, m0 = blockIdx.y * 128;
    const int wm = (wid & 3) * 32, wn = (wid >> 2) * 32;

    auto issue = [&](int j) {
        if (j < 4) {
            const int k0 = j * 64;
            const uint32_t st = sb + (j & 1) * XSTG;
#pragma unroll
            for (int i = 0; i < 4; i++) {           // A: 128x64 = 1024 x 16B
                int u = tid + (i << 8);
                int row = u >> 3, c = u & 7;
                cp_async16(st + row * XSTR_B + c * 16,
                           g_x16 + (size_t)(m0 + row) * II + k0 + c * 8);
            }
#pragma unroll
            for (int i = 0; i < 2; i++) {           // B: 64x64 = 512 x 16B
                int u = tid + (i << 8);
                int row = u >> 3, c = u & 7;
                cp_async16(st + XA_B + row * XSTR_B + c * 16,
                           g_Wih16 + (size_t)(n0 + row) * II + k0 + c * 8);
            }
        }
        cp_commit();
    };

    float acc[2][4][4];
#pragma unroll
    for (int mi = 0; mi < 2; mi++)
#pragma unroll
        for (int ni = 0; ni < 4; ni++)
#pragma unroll
            for (int v = 0; v < 4; v++) acc[mi][ni][v] = 0.f;

    issue(0); issue(1);
    for (int j = 0; j < 4; j++) {
        asm volatile("cp.async.wait_group 1;" ::: "memory");
        __syncthreads();
        const uint32_t st = sb + (j & 1) * XSTG;
#pragma unroll
        for (int u = 0; u < 4; u++) {               // k16 units
            uint32_t a[2][4], b[2][4];
            const uint32_t ab = st + (wm + (lane & 15)) * XSTR_B
                                   + (lane >> 4) * 16 + u * 32;
            ldm_x4(a[0], ab);
            ldm_x4(a[1], ab + 16 * XSTR_B);
            const uint32_t bb = st + XA_B + (wn + (lane & 15)) * XSTR_B
                                   + (lane >> 4) * 16 + u * 32;
            ldm_x4(b[0], bb);
            ldm_x4(b[1], bb + 16 * XSTR_B);
#pragma unroll
            for (int mi = 0; mi < 2; mi++)
#pragma unroll
                for (int nh = 0; nh < 2; nh++)
#pragma unroll
                    for (int sub = 0; sub < 2; sub++)
                        mma_fp16(acc[mi][nh * 2 + sub], a[mi],
                                 b[nh][sub], b[nh][sub + 2]);
        }
        __syncthreads();
        issue(j + 2);
    }

    // epilogue: add permuted bias, write fp32
    const int q = lane >> 2, r2 = (lane & 3) * 2;
#pragma unroll
    for (int mi = 0; mi < 2; mi++)
#pragma unroll
        for (int ni = 0; ni < 4; ni++) {
            int col = n0 + wn + ni * 8 + r2;
            float b0 = g_biasp[col], b1 = g_biasp[col + 1];
            int m = m0 + wm + mi * 16 + q;
            float2 v0 = {acc[mi][ni][0] + b0, acc[mi][ni][1] + b1};
            float2 v1 = {acc[mi][ni][2] + b0, acc[mi][ni][3] + b1};
            *(float2*)(g_xproj + (size_t)m * G4 + col) = v0;
            *(float2*)(g_xproj + (size_t)(m + 8) * G4 + col) = v1;
        }
}

// ======================= persistent LSTM, dataflow-synced ===================
__global__ __launch_bounds__(NTHR, 1) void lstm_persistent(
    float* __restrict__ out, const float* __restrict__ c0)
{
    extern __shared__ __align__(16) char smem[];
    const uint32_t sb = smem_to_u32(smem);
    const int tid = threadIdx.x;
    const int wid = tid >> 5, lane = tid & 31;
    const int bidx = blockIdx.x;
    const int n0g = bidx * NBLK;
    const int mgrp = wid & 3;
    const int warp_m = mgrp * 32;
    const int ks = wid >> 2;                 // 0..3
    const int barid = mgrp + 1;
    const int boff = bidx & 7;

    for (int i = tid; i < 4096; i += NTHR) {
        int row = i >> 7, gr = i & 127;
        cp_async16(sb + row * STRW_B + gr * 16,
                   g_W16 + (size_t)(n0g + row) * HH + gr * 8);
    }
    cp_commit();
    asm volatile("cp.async.wait_group 0;" ::: "memory");
    float* c_s = (float*)(smem + C_OFF);
    for (int i = tid; i < 1024; i += NTHR) {
        int row = i >> 3, hcl = i & 7;
        c_s[i] = c0[(size_t)row * HH + bidx * 8 + hcl];
    }
    __syncthreads();

    const uint32_t stg0 = sb + W_BYTES;
    const size_t OUT_H = (size_t)TT * BB * HH;
    const int q = lane >> 2, r4 = lane & 3;
    const bool writer = (r4 & 1) == 0;
    const int hl = r4 >> 1;
    const int gtid = ks * 32 + lane;

    for (int t = 0; t < TT; t++) {
        const int rb = t & 1, wb = rb ^ 1;
        const __half* hbase = g_h[rb];
        const unsigned* fl = g_flag + (size_t)(t - 1) * 32;

        if (ks == 0) {
            const float* xs = g_xproj + ((size_t)t * BB + warp_m) * G4 + n0g;
            const uint32_t xd = sb + XP_OFF + mgrp * 4608;
            for (int i = lane; i < 256; i += 32) {
                int row = i >> 3, c16 = i & 7;
                cp_async16(xd + row * 144 + c16 * 16,
                           xs + (size_t)row * G4 + c16 * 4);
            }
        }

        auto issueA = [&](int j, unsigned fv) {
            if (j < NCH) {
                const int jp = (j + boff) & 7;
                if (t > 0) {
                    const unsigned* fp = fl + jp * 4 + mgrp;
                    unsigned v = fv;
                    while (v < 16u) v = ld_acq(fp);
                }
                const int k0 = jp * KCH;
                const uint32_t st = stg0 + (j & 3) * STG_B + mgrp * GRP_B;
#pragma unroll
                for (int i4 = 0; i4 < 4; i4++) {
                    int u = gtid * 4 + i4;
                    int row = u >> 4, c16 = u & 15;
                    cp_async16(st + row * STRA_B + c16 * 16,
                               hbase + (size_t)(warp_m + row) * HH + k0 + c16 * 8);
                }
            }
            cp_commit();
        };
        auto probe = [&](int j) -> unsigned {
            if (t == 0 || j >= NCH) return 16u;
            return __ldcg(fl + ((j + boff) & 7) * 4 + mgrp);
        };

        float acc[2][4][4];
#pragma unroll
        for (int mi = 0; mi < 2; mi++)
#pragma unroll
            for (int nf = 0; nf < 4; nf++)
#pragma unroll
                for (int v = 0; v < 4; v++) acc[mi][nf][v] = 0.f;

        issueA(0, probe(0)); issueA(1, probe(1)); issueA(2, probe(2));
        unsigned fnext = probe(3);

        for (int j = 0; j < NCH; j++) {
            asm volatile("cp.async.wait_group 2;" ::: "memory");
            bar_named(barid, 128);

            const int jp = (j + boff) & 7;
            const uint32_t st = stg0 + (j & 3) * STG_B + mgrp * GRP_B;
            uint32_t a[2][2][4], b[2][2][4];
            const uint32_t abase = st + (lane & 15) * STRA_B
                                      + (lane >> 4) * 16 + ks * 64;
#pragma unroll
            for (int u = 0; u < 2; u++) {
                ldm_x4(a[0][u], abase + u * 32);
                ldm_x4(a[1][u], abase + u * 32 + 16 * STRA_B);
            }
#pragma unroll
            for (int u = 0; u < 2; u++) {
                const int kk = jp * KCH + ks * 32 + u * 16;
#pragma unroll
                for (int nh = 0; nh < 2; nh++) {
                    const uint32_t baddr = sb + (nh * 16 + (lane & 15)) * STRW_B
                                              + kk * 2 + (lane >> 4) * 16;
                    ldm_x4(b[u][nh], baddr);
                }
            }
            unsigned fcur = fnext;
            fnext = probe(j + 4);
            issueA(j + 3, fcur);

#pragma unroll
            for (int u = 0; u < 2; u++)
#pragma unroll
                for (int mi = 0; mi < 2; mi++)
#pragma unroll
                    for (int nh = 0; nh < 2; nh++)
#pragma unroll
                        for (int sub = 0; sub < 2; sub++)
                            mma_fp16(acc[mi][nh * 2 + sub], a[mi][u],
                                     b[u][nh][sub], b[u][nh][sub + 2]);
        }

        asm volatile("cp.async.wait_group 0;" ::: "memory");

        // ---- partial write: warp (mgrp, ks) parks acc in stage ks ----------
        {
            char* pw = smem + W_BYTES + ks * STG_B + mgrp * GRP_B;
#pragma unroll
            for (int mi = 0; mi < 2; mi++)
#pragma unroll
                for (int nf = 0; nf < 4; nf++)
                    *(float4*)(pw + (((mi * 4 + nf) * 32 + lane) << 4)) =
                        *(const float4*)acc[mi][nf];
        }
        bar_named(barid, 128);
        if (ks == 3 && lane == 0) red_rel(&g_ack[t]);   // all reads of rb done

        // ---- all-reduce slice: warp ks sums nf==ks from the other 3 -------
        float s0[2][4];
#pragma unroll
        for (int mi = 0; mi < 2; mi++)
#pragma unroll
            for (int v = 0; v < 4; v++) s0[mi][v] = acc[mi][ks][v];
#pragma unroll
        for (int s = 0; s < 4; s++) {
            if (s == ks) continue;
            const char* pr = smem + W_BYTES + s * STG_B + mgrp * GRP_B;
#pragma unroll
            for (int mi = 0; mi < 2; mi++) {
                float4 v = *(const float4*)
                    (pr + (((mi * 4 + ks) * 32 + lane) << 4));
                s0[mi][0] += v.x; s0[mi][1] += v.y;
                s0[mi][2] += v.z; s0[mi][3] += v.w;
            }
        }

        // ---- parallel epilogue: warp ks handles hcols 2ks, 2ks+1 ----------
        {
            const char* xps = smem + XP_OFF + mgrp * 4608;
            __half* hw = g_h[wb];
            float hnv[2][2], cnv[2][2];
#pragma unroll
            for (int mi = 0; mi < 2; mi++)
#pragma unroll
                for (int h = 0; h < 2; h++) {
                    float v0 = s0[mi][2 * h];
                    float v1 = s0[mi][2 * h + 1];
                    float p0 = __shfl_xor_sync(0xffffffffu, v0, 1);
                    float p1 = __shfl_xor_sync(0xffffffffu, v1, 1);
                    if (writer) {
                        int mr = mi * 16 + h * 8 + q;
                        int m = warp_m + mr;
                        int hcl = ks * 2 + hl;
                        float4 xv = *(const float4*)
                            (xps + mr * 144 + (ks * 8 + hl * 4) * 4);
                        float ig = fsig(v0 + xv.x);
                        float fg = fsig(v1 + xv.y);
                        float gg = ftanh(p0 + xv.z);
                        float og = fsig(p1 + xv.w);
                        int ci = m * 8 + hcl;
                        float cn = fg * c_s[ci] + ig * gg;
                        c_s[ci] = cn;
                        float hn = og * ftanh(cn);
                        cnv[mi][h] = cn; hnv[mi][h] = hn;
                        out[(size_t)t * BB * HH + (size_t)m * HH
                            + bidx * 8 + hcl] = hn;
                    }
                }
            if (t >= 1) {
                if (lane == 0) {
                    const unsigned* ap = &g_ack[t - 1];
                    unsigned v = __ldcg(ap);
                    while (v < 512u) v = ld_acq(ap);
                }
                __syncwarp();
            }
#pragma unroll
            for (int mi = 0; mi < 2; mi++)
#pragma unroll
                for (int h = 0; h < 2; h++)
                    if (writer) {
                        int m = warp_m + mi * 16 + h * 8 + q;
                        int hc = bidx * 8 + ks * 2 + hl;
                        size_t oidx = (size_t)m * HH + hc;
                        __stcg(&hw[oidx], __float2half(hnv[mi][h]));
                        if (t == TT - 1) {
                            out[OUT_H + oidx] = hnv[mi][h];
                            out[OUT_H + (size_t)BB * HH + oidx] = cnv[mi][h];
                        }
                    }
        }
        bar_named(barid, 128);   // h stored by all 4 warps; stages reusable
        if (ks == 0 && lane == 0)
            red_rel(&g_flag[(size_t)t * 32 + (bidx >> 4) * 4 + mgrp]);
    }
}

// ============================================================================
extern "C" void kernel_launch(void* const* d_in, const int* in_sizes, int n_in,
                              void* d_out, int out_size) {
    const float* inputs = (const float*)d_in[0];
    const float* h0     = (const float*)d_in[1];
    const float* c0     = (const float*)d_in[2];
    const float* W_ih   = (const float*)d_in[3];
    const float* W_hh   = (const float*)d_in[4];
    const float* b_ih   = (const float*)d_in[5];
    const float* b_hh   = (const float*)d_in[6];
    float* out = (float*)d_out;

    cudaFuncSetAttribute(lstm_persistent,
                         cudaFuncAttributeMaxDynamicSharedMemorySize, SMEM_TOTAL);
    cudaFuncSetAttribute(xproj16_kernel,
                         cudaFuncAttributeMaxDynamicSharedMemorySize, XSMEM);

    init_state<<<(BB * HH + 255) / 256, 256>>>(h0);
    wsplit_kernel<<<(int)(((size_t)G4 * HH + 255) / 256), 256>>>(W_hh);
    conv_x16<<<(int)(((size_t)TT * BB * II + 255) / 256), 256>>>(inputs);
    conv_wih<<<(G4 * II + 255) / 256, 256>>>(W_ih, b_ih, b_hh);

    dim3 xgrid(G4 / 64, (TT * BB) / 128);
    xproj16_kernel<<<xgrid, 256, XSMEM>>>();

    lstm_persistent<<<GRIDN, NTHR, SMEM_TOTAL>>>(out, c0);
}

// round 14
// speedup vs baseline: 1.7872x; 1.0442x over previous
#include <cuda_runtime.h>
#include <cuda_fp16.h>
#include <cstdint>
#include <math.h>

#define TT 512
#define BB 128
#define II 256
#define HH 1024
#define G4 (4 * HH)
#define NBLK 32               // gate-cols per block (8 hcols)
#define GRIDN 128
#define NTHR 512              // 16 warps: 4(M) x 4(KS)
#define KCH 128
#define NCH (HH / KCH)        // 8 chunks per step
#define STRW_B 2064           // W smem row stride: 1024 fp16 + 16B pad
#define STRA_B 272            // A smem row stride: 128 fp16 (256B) + 16B pad
#define W_BYTES (NBLK * STRW_B)          // 66048
#define GRP_B (32 * STRA_B)              // 8704
#define STG_B (4 * GRP_B)                // 34816
#define NSTAGE 4
#define XP_OFF (W_BYTES + NSTAGE * STG_B)   // 205312
#define C_OFF (XP_OFF + 4 * 4608)           // 223744
#define SMEM_TOTAL (C_OFF + 4096)           // 227840

// xproj fp16 GEMM tiling
#define XSTR_B 144            // 64 fp16 + 16B pad
#define XA_B (128 * XSTR_B)   // 18432
#define XB_B (64 * XSTR_B)    // 9216
#define XSTG (XA_B + XB_B)    // 27648
#define XSMEM (2 * XSTG)      // 55296

// ---------------- scratch ---------------------------------------------------
__device__ float g_xproj[(size_t)TT * BB * G4];
__device__ __half g_h[3][BB * HH];           // TRIPLE-buffered h (fp16)
__device__ __half g_W16[(size_t)G4 * HH];    // fp16 W_hh, gate-interleaved rows
__device__ __half g_x16[(size_t)TT * BB * II];
__device__ __half g_Wih16[(size_t)G4 * II];  // fp16 W_ih, gate-interleaved rows
__device__ float g_biasp[G4];                // permuted b_ih+b_hh
__device__ unsigned g_flag[TT * 32];         // [t][chunk 0..7][mgrp] -> 16

// ======================= helpers =============================================
__device__ __forceinline__ uint32_t smem_to_u32(const void* p) {
    uint32_t a;
    asm("{ .reg .u64 t; cvta.to.shared.u64 t, %1; cvt.u32.u64 %0, t; }"
        : "=r"(a) : "l"(p));
    return a;
}
__device__ __forceinline__ void cp_async16(uint32_t dst, const void* src) {
    size_t gsrc = __cvta_generic_to_global(src);
    asm volatile("cp.async.cg.shared.global [%0], [%1], 16;"
                 :: "r"(dst), "l"(gsrc) : "memory");
}
__device__ __forceinline__ void cp_commit() {
    asm volatile("cp.async.commit_group;" ::: "memory");
}
__device__ __forceinline__ void bar_named(int id, int cnt) {
    asm volatile("bar.sync %0, %1;" :: "r"(id), "r"(cnt) : "memory");
}
__device__ __forceinline__ void ldm_x4(uint32_t* r, uint32_t addr) {
    asm volatile("ldmatrix.sync.aligned.m8n8.x4.shared.b16 {%0,%1,%2,%3}, [%4];"
                 : "=r"(r[0]), "=r"(r[1]), "=r"(r[2]), "=r"(r[3]) : "r"(addr));
}
__device__ __forceinline__ void mma_fp16(float* d, const uint32_t* a,
                                         uint32_t b0, uint32_t b1) {
    asm volatile(
        "mma.sync.aligned.m16n8k16.row.col.f32.f16.f16.f32 "
        "{%0,%1,%2,%3}, {%4,%5,%6,%7}, {%8,%9}, {%0,%1,%2,%3};"
        : "+f"(d[0]), "+f"(d[1]), "+f"(d[2]), "+f"(d[3])
        : "r"(a[0]), "r"(a[1]), "r"(a[2]), "r"(a[3]), "r"(b0), "r"(b1));
}
__device__ __forceinline__ unsigned ld_acq(const unsigned* p) {
    unsigned v;
    asm volatile("ld.acquire.gpu.global.u32 %0, [%1];" : "=r"(v) : "l"(p));
    return v;
}
__device__ __forceinline__ void red_rel(unsigned* p) {
    asm volatile("red.release.gpu.global.add.u32 [%0], 1;" :: "l"(p) : "memory");
}
__device__ __forceinline__ float fsig(float x) {
    x = fminf(fmaxf(x, -20.f), 20.f);
    return __fdividef(1.f, 1.f + __expf(-x));
}
__device__ __forceinline__ float ftanh(float x) {
    x = fminf(fmaxf(x, -20.f), 20.f);
    float e = __expf(-2.f * x);
    return __fdividef(1.f - e, 1.f + e);
}

// ======================= init / convert kernels =============================
__global__ void init_state(const float* __restrict__ h0) {
    int i = blockIdx.x * blockDim.x + threadIdx.x;
    if (i < BB * HH) g_h[0][i] = __float2half(h0[i]);
    if (i < TT * 32) g_flag[i] = 0u;
}

__global__ void wsplit_kernel(const float* __restrict__ W) {
    size_t i = (size_t)blockIdx.x * blockDim.x + threadIdx.x;
    if (i < (size_t)G4 * HH) {
        int n = (int)(i / HH), k = (int)(i % HH);
        int r = ((n & 1023) << 2) | (n >> 10);   // gate-interleaved perm
        g_W16[(size_t)r * HH + k] = __float2half(W[i]);
    }
}

__global__ void conv_x16(const float* __restrict__ inp) {
    size_t i = (size_t)blockIdx.x * blockDim.x + threadIdx.x;
    if (i < (size_t)TT * BB * II) g_x16[i] = __float2half(inp[i]);
}

__global__ void conv_wih(const float* __restrict__ W_ih,
                         const float* __restrict__ b_ih,
                         const float* __restrict__ b_hh) {
    int i = blockIdx.x * blockDim.x + threadIdx.x;
    if (i < G4 * II) {
        int n = i >> 8, k = i & 255;
        int r = ((n & 1023) << 2) | (n >> 10);
        g_Wih16[(size_t)r * II + k] = __float2half(W_ih[i]);
        if (k == 0) g_biasp[r] = b_ih[n] + b_hh[n];
    }
}

// ======================= xproj fp16 HMMA GEMM ================================
__global__ __launch_bounds__(256) void xproj16_kernel() {
    extern __shared__ __align__(16) char smx[];
    const uint32_t sb = smem_to_u32(smx);
    const int tid = threadIdx.x, wid = tid >> 5, lane = tid & 31;
    const int n0 = blockIdx.x * 64, m0 = blockIdx.y * 128;
    const int wm = (wid & 3) * 32, wn = (wid >> 2) * 32;

    auto issue = [&](int j) {
        if (j < 4) {
            const int k0 = j * 64;
            const uint32_t st = sb + (j & 1) * XSTG;
#pragma unroll
            for (int i = 0; i < 4; i++) {
                int u = tid + (i << 8);
                int row = u >> 3, c = u & 7;
                cp_async16(st + row * XSTR_B + c * 16,
                           g_x16 + (size_t)(m0 + row) * II + k0 + c * 8);
            }
#pragma unroll
            for (int i = 0; i < 2; i++) {
                int u = tid + (i << 8);
                int row = u >> 3, c = u & 7;
                cp_async16(st + XA_B + row * XSTR_B + c * 16,
                           g_Wih16 + (size_t)(n0 + row) * II + k0 + c * 8);
            }
        }
        cp_commit();
    };

    float acc[2][4][4];
#pragma unroll
    for (int mi = 0; mi < 2; mi++)
#pragma unroll
        for (int ni = 0; ni < 4; ni++)
#pragma unroll
            for (int v = 0; v < 4; v++) acc[mi][ni][v] = 0.f;

    issue(0); issue(1);
    for (int j = 0; j < 4; j++) {
        asm volatile("cp.async.wait_group 1;" ::: "memory");
        __syncthreads();
        const uint32_t st = sb + (j & 1) * XSTG;
#pragma unroll
        for (int u = 0; u < 4; u++) {
            uint32_t a[2][4], b[2][4];
            const uint32_t ab = st + (wm + (lane & 15)) * XSTR_B
                                   + (lane >> 4) * 16 + u * 32;
            ldm_x4(a[0], ab);
            ldm_x4(a[1], ab + 16 * XSTR_B);
            const uint32_t bb = st + XA_B + (wn + (lane & 15)) * XSTR_B
                                   + (lane >> 4) * 16 + u * 32;
            ldm_x4(b[0], bb);
            ldm_x4(b[1], bb + 16 * XSTR_B);
#pragma unroll
            for (int mi = 0; mi < 2; mi++)
#pragma unroll
                for (int nh = 0; nh < 2; nh++)
#pragma unroll
                    for (int sub = 0; sub < 2; sub++)
                        mma_fp16(acc[mi][nh * 2 + sub], a[mi],
                                 b[nh][sub], b[nh][sub + 2]);
        }
        __syncthreads();
        issue(j + 2);
    }

    const int q = lane >> 2, r2 = (lane & 3) * 2;
#pragma unroll
    for (int mi = 0; mi < 2; mi++)
#pragma unroll
        for (int ni = 0; ni < 4; ni++) {
            int col = n0 + wn + ni * 8 + r2;
            float b0 = g_biasp[col], b1 = g_biasp[col + 1];
            int m = m0 + wm + mi * 16 + q;
            float2 v0 = {acc[mi][ni][0] + b0, acc[mi][ni][1] + b1};
            float2 v1 = {acc[mi][ni][2] + b0, acc[mi][ni][3] + b1};
            *(float2*)(g_xproj + (size_t)m * G4 + col) = v0;
            *(float2*)(g_xproj + (size_t)(m + 8) * G4 + col) = v1;
        }
}

// ======================= persistent LSTM, dataflow-synced ===================
// Triple-buffered h: step t reads g_h[t%3], writes g_h[(t+1)%3]. The flag
// transitive chain guarantees all blocks finished reading h_{t-2} before any
// block can write h_{t+1} into that buffer (see R14 proof) — no ack needed.
__global__ __launch_bounds__(NTHR, 1) void lstm_persistent(
    float* __restrict__ out, const float* __restrict__ c0)
{
    extern __shared__ __align__(16) char smem[];
    const uint32_t sb = smem_to_u32(smem);
    const int tid = threadIdx.x;
    const int wid = tid >> 5, lane = tid & 31;
    const int bidx = blockIdx.x;
    const int n0g = bidx * NBLK;
    const int mgrp = wid & 3;
    const int warp_m = mgrp * 32;
    const int ks = wid >> 2;                 // 0..3
    const int barid = mgrp + 1;
    const int boff = bidx & 7;

    for (int i = tid; i < 4096; i += NTHR) {
        int row = i >> 7, gr = i & 127;
        cp_async16(sb + row * STRW_B + gr * 16,
                   g_W16 + (size_t)(n0g + row) * HH + gr * 8);
    }
    cp_commit();
    asm volatile("cp.async.wait_group 0;" ::: "memory");
    float* c_s = (float*)(smem + C_OFF);
    for (int i = tid; i < 1024; i += NTHR) {
        int row = i >> 3, hcl = i & 7;
        c_s[i] = c0[(size_t)row * HH + bidx * 8 + hcl];
    }
    __syncthreads();

    const uint32_t stg0 = sb + W_BYTES;
    const size_t OUT_H = (size_t)TT * BB * HH;
    const int q = lane >> 2, r4 = lane & 3;
    const bool writer = (r4 & 1) == 0;
    const int hl = r4 >> 1;
    const int gtid = ks * 32 + lane;

    int rb = 0;                               // t % 3
    for (int t = 0; t < TT; t++) {
        const int wb = (rb == 2) ? 0 : rb + 1;
        const __half* hbase = g_h[rb];
        const unsigned* fl = g_flag + (size_t)(t - 1) * 32;

        if (ks == 0) {
            const float* xs = g_xproj + ((size_t)t * BB + warp_m) * G4 + n0g;
            const uint32_t xd = sb + XP_OFF + mgrp * 4608;
            for (int i = lane; i < 256; i += 32) {
                int row = i >> 3, c16 = i & 7;
                cp_async16(xd + row * 144 + c16 * 16,
                           xs + (size_t)row * G4 + c16 * 4);
            }
        }

        auto issueA = [&](int j, unsigned fv) {
            if (j < NCH) {
                const int jp = (j + boff) & 7;
                if (t > 0) {
                    const unsigned* fp = fl + jp * 4 + mgrp;
                    unsigned v = fv;
                    while (v < 16u) v = ld_acq(fp);
                }
                const int k0 = jp * KCH;
                const uint32_t st = stg0 + (j & 3) * STG_B + mgrp * GRP_B;
#pragma unroll
                for (int i4 = 0; i4 < 4; i4++) {
                    int u = gtid * 4 + i4;
                    int row = u >> 4, c16 = u & 15;
                    cp_async16(st + row * STRA_B + c16 * 16,
                               hbase + (size_t)(warp_m + row) * HH + k0 + c16 * 8);
                }
            }
            cp_commit();
        };
        auto probe = [&](int j) -> unsigned {
            if (t == 0 || j >= NCH) return 16u;
            return __ldcg(fl + ((j + boff) & 7) * 4 + mgrp);
        };

        float acc[2][4][4];
#pragma unroll
        for (int mi = 0; mi < 2; mi++)
#pragma unroll
            for (int nf = 0; nf < 4; nf++)
#pragma unroll
                for (int v = 0; v < 4; v++) acc[mi][nf][v] = 0.f;

        issueA(0, probe(0)); issueA(1, probe(1)); issueA(2, probe(2));
        unsigned fnext = probe(3);

        for (int j = 0; j < NCH; j++) {
            asm volatile("cp.async.wait_group 2;" ::: "memory");
            bar_named(barid, 128);

            const int jp = (j + boff) & 7;
            const uint32_t st = stg0 + (j & 3) * STG_B + mgrp * GRP_B;
            uint32_t a[2][2][4], b[2][2][4];
            const uint32_t abase = st + (lane & 15) * STRA_B
                                      + (lane >> 4) * 16 + ks * 64;
#pragma unroll
            for (int u = 0; u < 2; u++) {
                ldm_x4(a[0][u], abase + u * 32);
                ldm_x4(a[1][u], abase + u * 32 + 16 * STRA_B);
            }
#pragma unroll
            for (int u = 0; u < 2; u++) {
                const int kk = jp * KCH + ks * 32 + u * 16;
#pragma unroll
                for (int nh = 0; nh < 2; nh++) {
                    const uint32_t baddr = sb + (nh * 16 + (lane & 15)) * STRW_B
                                              + kk * 2 + (lane >> 4) * 16;
                    ldm_x4(b[u][nh], baddr);
                }
            }
            unsigned fcur = fnext;
            fnext = probe(j + 4);
            issueA(j + 3, fcur);

#pragma unroll
            for (int u = 0; u < 2; u++)
#pragma unroll
                for (int mi = 0; mi < 2; mi++)
#pragma unroll
                    for (int nh = 0; nh < 2; nh++)
#pragma unroll
                        for (int sub = 0; sub < 2; sub++)
                            mma_fp16(acc[mi][nh * 2 + sub], a[mi][u],
                                     b[u][nh][sub], b[u][nh][sub + 2]);
        }

        asm volatile("cp.async.wait_group 0;" ::: "memory");

        // ---- partial write: warp (mgrp, ks) parks acc in stage ks ----------
        {
            char* pw = smem + W_BYTES + ks * STG_B + mgrp * GRP_B;
#pragma unroll
            for (int mi = 0; mi < 2; mi++)
#pragma unroll
                for (int nf = 0; nf < 4; nf++)
                    *(float4*)(pw + (((mi * 4 + nf) * 32 + lane) << 4)) =
                        *(const float4*)acc[mi][nf];
        }
        bar_named(barid, 128);

        // ---- all-reduce slice: warp ks sums nf==ks from the other 3 -------
        float s0[2][4];
#pragma unroll
        for (int mi = 0; mi < 2; mi++)
#pragma unroll
            for (int v = 0; v < 4; v++) s0[mi][v] = acc[mi][ks][v];
#pragma unroll
        for (int s = 0; s < 4; s++) {
            if (s == ks) continue;
            const char* pr = smem + W_BYTES + s * STG_B + mgrp * GRP_B;
#pragma unroll
            for (int mi = 0; mi < 2; mi++) {
                float4 v = *(const float4*)
                    (pr + (((mi * 4 + ks) * 32 + lane) << 4));
                s0[mi][0] += v.x; s0[mi][1] += v.y;
                s0[mi][2] += v.z; s0[mi][3] += v.w;
            }
        }

        // ---- parallel epilogue: warp ks handles hcols 2ks, 2ks+1 ----------
        {
            const char* xps = smem + XP_OFF + mgrp * 4608;
            __half* hw = g_h[wb];
#pragma unroll
            for (int mi = 0; mi < 2; mi++)
#pragma unroll
                for (int h = 0; h < 2; h++) {
                    float v0 = s0[mi][2 * h];
                    float v1 = s0[mi][2 * h + 1];
                    float p0 = __shfl_xor_sync(0xffffffffu, v0, 1);
                    float p1 = __shfl_xor_sync(0xffffffffu, v1, 1);
                    if (writer) {
                        int mr = mi * 16 + h * 8 + q;
                        int m = warp_m + mr;
                        int hcl = ks * 2 + hl;
                        int hc = bidx * 8 + hcl;
                        float4 xv = *(const float4*)
                            (xps + mr * 144 + (ks * 8 + hl * 4) * 4);
                        float ig = fsig(v0 + xv.x);
                        float fg = fsig(v1 + xv.y);
                        float gg = ftanh(p0 + xv.z);
                        float og = fsig(p1 + xv.w);
                        int ci = m * 8 + hcl;
                        float cn = fg * c_s[ci] + ig * gg;
                        c_s[ci] = cn;
                        float hn = og * ftanh(cn);
                        size_t oidx = (size_t)m * HH + hc;
                        out[(size_t)t * BB * HH + oidx] = hn;
                        __stcg(&hw[oidx], __float2half(hn));
                        if (t == TT - 1) {
                            out[OUT_H + oidx] = hn;
                            out[OUT_H + (size_t)BB * HH + oidx] = cn;
                        }
                    }
                }
        }
        bar_named(barid, 128);   // h stored by all 4 warps; stages reusable
        if (ks == 0 && lane == 0)
            red_rel(&g_flag[(size_t)t * 32 + (bidx >> 4) * 4 + mgrp]);

        rb = wb;
    }
}

// ============================================================================
extern "C" void kernel_launch(void* const* d_in, const int* in_sizes, int n_in,
                              void* d_out, int out_size) {
    const float* inputs = (const float*)d_in[0];
    const float* h0     = (const float*)d_in[1];
    const float* c0     = (const float*)d_in[2];
    const float* W_ih   = (const float*)d_in[3];
    const float* W_hh   = (const float*)d_in[4];
    const float* b_ih   = (const float*)d_in[5];
    const float* b_hh   = (const float*)d_in[6];
    float* out = (float*)d_out;

    cudaFuncSetAttribute(lstm_persistent,
                         cudaFuncAttributeMaxDynamicSharedMemorySize, SMEM_TOTAL);
    cudaFuncSetAttribute(xproj16_kernel,
                         cudaFuncAttributeMaxDynamicSharedMemorySize, XSMEM);

    init_state<<<(BB * HH + 255) / 256, 256>>>(h0);
    wsplit_kernel<<<(int)(((size_t)G4 * HH + 255) / 256), 256>>>(W_hh);
    conv_x16<<<(int)(((size_t)TT * BB * II + 255) / 256), 256>>>(inputs);
    conv_wih<<<(G4 * II + 255) / 256, 256>>>(W_ih, b_ih, b_hh);

    dim3 xgrid(G4 / 64, (TT * BB) / 128);
    xproj16_kernel<<<xgrid, 256, XSMEM>>>();

    lstm_persistent<<<GRIDN, NTHR, SMEM_TOTAL>>>(out, c0);
}

// round 16
// speedup vs baseline: 1.8373x; 1.0280x over previous
#include <cuda_runtime.h>
#include <cuda_fp16.h>
#include <cstdint>
#include <math.h>

#define TT 512
#define BB 128
#define II 256
#define HH 1024
#define G4 (4 * HH)
#define NBLK 32               // gate-cols per block (8 hcols)
#define GRIDN 128
#define NTHR 512              // 16 warps: 4(M) x 4(KS)
#define KCH 128
#define NCH (HH / KCH)        // 8 chunks per step
#define STRW_B 2064           // W smem row stride: 1024 fp16 + 16B pad
#define W_BYTES (NBLK * STRW_B)          // 66048
#define WTILE_B 2048          // per-warp A tile: 32 rows x 64B, swizzled
#define STG_B (16 * WTILE_B)  // 32768 per stage
#define NSTAGE 4
#define XP_OFF (W_BYTES + NSTAGE * STG_B)   // 197120
#define C_OFF (XP_OFF + 4 * 4608)           // 215552
#define SMEM_TOTAL (C_OFF + 4096)           // 219648

// ---------------- scratch ---------------------------------------------------
__device__ float g_xproj[(size_t)TT * BB * G4];
__device__ __half g_h[3][BB * HH];           // triple-buffered h (fp16)
__device__ __half g_W16[(size_t)G4 * HH];    // fp16 W_hh, gate-interleaved rows
__device__ __half g_x16[(size_t)TT * BB * II];
__device__ __half g_Wih16[(size_t)G4 * II];
__device__ float g_biasp[G4];
__device__ unsigned g_flag[TT * 32];         // [t][chunk 0..7][mgrp] -> 16

// ======================= helpers =============================================
__device__ __forceinline__ uint32_t smem_to_u32(const void* p) {
    uint32_t a;
    asm("{ .reg .u64 t; cvta.to.shared.u64 t, %1; cvt.u32.u64 %0, t; }"
        : "=r"(a) : "l"(p));
    return a;
}
__device__ __forceinline__ void cp_async16(uint32_t dst, const void* src) {
    size_t gsrc = __cvta_generic_to_global(src);
    asm volatile("cp.async.cg.shared.global [%0], [%1], 16;"
                 :: "r"(dst), "l"(gsrc) : "memory");
}
__device__ __forceinline__ void cp_commit() {
    asm volatile("cp.async.commit_group;" ::: "memory");
}
__device__ __forceinline__ void bar_named(int id, int cnt) {
    asm volatile("bar.sync %0, %1;" :: "r"(id), "r"(cnt) : "memory");
}
__device__ __forceinline__ void ldm_x4(uint32_t* r, uint32_t addr) {
    asm volatile("ldmatrix.sync.aligned.m8n8.x4.shared.b16 {%0,%1,%2,%3}, [%4];"
                 : "=r"(r[0]), "=r"(r[1]), "=r"(r[2]), "=r"(r[3]) : "r"(addr));
}
__device__ __forceinline__ void mma_fp16(float* d, const uint32_t* a,
                                         uint32_t b0, uint32_t b1) {
    asm volatile(
        "mma.sync.aligned.m16n8k16.row.col.f32.f16.f16.f32 "
        "{%0,%1,%2,%3}, {%4,%5,%6,%7}, {%8,%9}, {%0,%1,%2,%3};"
        : "+f"(d[0]), "+f"(d[1]), "+f"(d[2]), "+f"(d[3])
        : "r"(a[0]), "r"(a[1]), "r"(a[2]), "r"(a[3]), "r"(b0), "r"(b1));
}
__device__ __forceinline__ unsigned ld_acq(const unsigned* p) {
    unsigned v;
    asm volatile("ld.acquire.gpu.global.u32 %0, [%1];" : "=r"(v) : "l"(p));
    return v;
}
__device__ __forceinline__ void red_rel(unsigned* p) {
    asm volatile("red.release.gpu.global.add.u32 [%0], 1;" :: "l"(p) : "memory");
}
__device__ __forceinline__ float fsig(float x) {
    x = fminf(fmaxf(x, -20.f), 20.f);
    return __fdividef(1.f, 1.f + __expf(-x));
}
__device__ __forceinline__ float ftanh(float x) {
    x = fminf(fmaxf(x, -20.f), 20.f);
    float e = __expf(-2.f * x);
    return __fdividef(1.f - e, 1.f + e);
}

// ======================= init / convert kernels =============================
__global__ void init_state(const float* __restrict__ h0) {
    int i = blockIdx.x * blockDim.x + threadIdx.x;
    if (i < BB * HH) g_h[0][i] = __float2half(h0[i]);
    if (i < TT * 32) g_flag[i] = 0u;
}

__global__ void wsplit_kernel(const float* __restrict__ W) {
    size_t i = (size_t)blockIdx.x * blockDim.x + threadIdx.x;
    if (i < (size_t)G4 * HH) {
        int n = (int)(i / HH), k = (int)(i % HH);
        int r = ((n & 1023) << 2) | (n >> 10);
        g_W16[(size_t)r * HH + k] = __float2half(W[i]);
    }
}

__global__ void conv_x16(const float* __restrict__ inp) {
    size_t i = (size_t)blockIdx.x * blockDim.x + threadIdx.x;
    if (i < (size_t)TT * BB * II) g_x16[i] = __float2half(inp[i]);
}

__global__ void conv_wih(const float* __restrict__ W_ih,
                         const float* __restrict__ b_ih,
                         const float* __restrict__ b_hh) {
    int i = blockIdx.x * blockDim.x + threadIdx.x;
    if (i < G4 * II) {
        int n = i >> 8, k = i & 255;
        int r = ((n & 1023) << 2) | (n >> 10);
        g_Wih16[(size_t)r * II + k] = __float2half(W_ih[i]);
        if (k == 0) g_biasp[r] = b_ih[n] + b_hh[n];
    }
}

// ======================= xproj fp16 HMMA GEMM ================================
#define XSTR_B 144
#define XA_B (128 * XSTR_B)
#define XB_B (64 * XSTR_B)
#define XSTG (XA_B + XB_B)
#define XSMEM (2 * XSTG)

__global__ __launch_bounds__(256) void xproj16_kernel() {
    extern __shared__ __align__(16) char smx[];
    const uint32_t sb = smem_to_u32(smx);
    const int tid = threadIdx.x, wid = tid >> 5, lane = tid & 31;
    const int n0 = blockIdx.x * 64, m0 = blockIdx.y * 128;
    const int wm = (wid & 3) * 32, wn = (wid >> 2) * 32;

    auto issue = [&](int j) {
        if (j < 4) {
            const int k0 = j * 64;
            const uint32_t st = sb + (j & 1) * XSTG;
#pragma unroll
            for (int i = 0; i < 4; i++) {
                int u = tid + (i << 8);
                int row = u >> 3, c = u & 7;
                cp_async16(st + row * XSTR_B + c * 16,
                           g_x16 + (size_t)(m0 + row) * II + k0 + c * 8);
            }
#pragma unroll
            for (int i = 0; i < 2; i++) {
                int u = tid + (i << 8);
                int row = u >> 3, c = u & 7;
                cp_async16(st + XA_B + row * XSTR_B + c * 16,
                           g_Wih16 + (size_t)(n0 + row) * II + k0 + c * 8);
            }
        }
        cp_commit();
    };

    float acc[2][4][4];
#pragma unroll
    for (int mi = 0; mi < 2; mi++)
#pragma unroll
        for (int ni = 0; ni < 4; ni++)
#pragma unroll
            for (int v = 0; v < 4; v++) acc[mi][ni][v] = 0.f;

    issue(0); issue(1);
    for (int j = 0; j < 4; j++) {
        asm volatile("cp.async.wait_group 1;" ::: "memory");
        __syncthreads();
        const uint32_t st = sb + (j & 1) * XSTG;
#pragma unroll
        for (int u = 0; u < 4; u++) {
            uint32_t a[2][4], b[2][4];
            const uint32_t ab = st + (wm + (lane & 15)) * XSTR_B
                                   + (lane >> 4) * 16 + u * 32;
            ldm_x4(a[0], ab);
            ldm_x4(a[1], ab + 16 * XSTR_B);
            const uint32_t bb = st + XA_B + (wn + (lane & 15)) * XSTR_B
                                   + (lane >> 4) * 16 + u * 32;
            ldm_x4(b[0], bb);
            ldm_x4(b[1], bb + 16 * XSTR_B);
#pragma unroll
            for (int mi = 0; mi < 2; mi++)
#pragma unroll
                for (int nh = 0; nh < 2; nh++)
#pragma unroll
                    for (int sub = 0; sub < 2; sub++)
                        mma_fp16(acc[mi][nh * 2 + sub], a[mi],
                                 b[nh][sub], b[nh][sub + 2]);
        }
        __syncthreads();
        issue(j + 2);
    }

    const int q = lane >> 2, r2 = (lane & 3) * 2;
#pragma unroll
    for (int mi = 0; mi < 2; mi++)
#pragma unroll
        for (int ni = 0; ni < 4; ni++) {
            int col = n0 + wn + ni * 8 + r2;
            float b0 = g_biasp[col], b1 = g_biasp[col + 1];
            int m = m0 + wm + mi * 16 + q;
            float2 v0 = {acc[mi][ni][0] + b0, acc[mi][ni][1] + b1};
            float2 v1 = {acc[mi][ni][2] + b0, acc[mi][ni][3] + b1};
            *(float2*)(g_xproj + (size_t)m * G4 + col) = v0;
            *(float2*)(g_xproj + (size_t)(m + 8) * G4 + col) = v1;
        }
}

// ======================= persistent LSTM, per-warp pipelines ================
// Per-warp private swizzled A tiles (no mainloop barriers). Memory layout is
// mgrp-confined: stage j tile of warp (mgrp, ks) at mgrp*8192 + ks*2048 in
// each 32KB stage; partials of (mgrp, ks) live in stages 0-1 at the SAME
// mgrp slice — so no region is ever shared across m-groups, and the 3 named
// bars per step (post-mainloop, post-partial, post-epilogue) give all
// intra-mgrp ordering.
__global__ __launch_bounds__(NTHR, 1) void lstm_persistent(
    float* __restrict__ out, const float* __restrict__ c0)
{
    extern __shared__ __align__(16) char smem[];
    const uint32_t sb = smem_to_u32(smem);
    const int tid = threadIdx.x;
    const int wid = tid >> 5, lane = tid & 31;
    const int bidx = blockIdx.x;
    const int n0g = bidx * NBLK;
    const int mgrp = wid & 3;
    const int warp_m = mgrp * 32;
    const int ks = wid >> 2;                 // 0..3 (32 k each)
    const int barid = mgrp + 1;
    const int boff = bidx & 7;

    for (int i = tid; i < 4096; i += NTHR) {
        int row = i >> 7, gr = i & 127;
        cp_async16(sb + row * STRW_B + gr * 16,
                   g_W16 + (size_t)(n0g + row) * HH + gr * 8);
    }
    cp_commit();
    asm volatile("cp.async.wait_group 0;" ::: "memory");
    float* c_s = (float*)(smem + C_OFF);
    for (int i = tid; i < 1024; i += NTHR) {
        int row = i >> 3, hcl = i & 7;
        c_s[i] = c0[(size_t)row * HH + bidx * 8 + hcl];
    }
    __syncthreads();

    const size_t OUT_H = (size_t)TT * BB * HH;
    const int q = lane >> 2, r4 = lane & 3;
    const bool writer = (r4 & 1) == 0;
    const int hl = r4 >> 1;
    const int swl = (lane >> 1) & 3;         // row-swizzle key (row = lane)
    // mgrp-confined tile/partial addressing
    const uint32_t mslice = mgrp * 8192 + ks * 2048;
    const uint32_t ppart = W_BYTES + (ks >> 1) * STG_B + mgrp * 8192
                         + (ks & 1) * 4096;

    int rb = 0;                               // t % 3
    for (int t = 0; t < TT; t++) {
        const int wb = (rb == 2) ? 0 : rb + 1;
        const __half* hbase = g_h[rb];
        const unsigned* fl = g_flag + (size_t)(t - 1) * 32;

        if (ks == 0) {
            const float* xs = g_xproj + ((size_t)t * BB + warp_m) * G4 + n0g;
            const uint32_t xd = sb + XP_OFF + mgrp * 4608;
            for (int i = lane; i < 256; i += 32) {
                int row = i >> 3, c16 = i & 7;
                cp_async16(xd + row * 144 + c16 * 16,
                           xs + (size_t)row * G4 + c16 * 4);
            }
        }

        // per-warp A load: 32 rows (row = lane) x 32 k (this warp's quarter)
        auto issueA = [&](int j, unsigned fv) {
            if (j < NCH) {
                const int jp = (j + boff) & 7;
                if (t > 0) {
                    const unsigned* fp = fl + jp * 4 + mgrp;
                    unsigned v = fv;
                    while (v < 16u) v = ld_acq(fp);
                }
                const int k0 = jp * KCH + ks * 32;
                const uint32_t rbase = sb + W_BYTES + (j & 3) * STG_B
                                          + mslice + lane * 64;
                const __half* srow = hbase + (size_t)(warp_m + lane) * HH + k0;
#pragma unroll
                for (int u = 0; u < 4; u++)
                    cp_async16(rbase + ((u ^ swl) << 4), srow + u * 8);
            }
            cp_commit();
        };
        auto probe = [&](int j) -> unsigned {
            if (t == 0 || j >= NCH) return 16u;
            return __ldcg(fl + ((j + boff) & 7) * 4 + mgrp);
        };

        float acc[2][4][4];
#pragma unroll
        for (int mi = 0; mi < 2; mi++)
#pragma unroll
            for (int nf = 0; nf < 4; nf++)
#pragma unroll
                for (int v = 0; v < 4; v++) acc[mi][nf][v] = 0.f;

        issueA(0, probe(0)); issueA(1, probe(1)); issueA(2, probe(2));
        unsigned fnext = probe(3);

        for (int j = 0; j < NCH; j++) {
            asm volatile("cp.async.wait_group 2;" ::: "memory");
            __syncwarp();

            const int jp = (j + boff) & 7;
            const uint32_t stile = sb + W_BYTES + (j & 3) * STG_B + mslice;
            uint32_t a[2][2][4], b[2][2][4];
#pragma unroll
            for (int u = 0; u < 2; u++) {
#pragma unroll
                for (int mi = 0; mi < 2; mi++) {
                    int row = mi * 16 + (lane & 15);
                    int segk = 2 * u + (lane >> 4);
                    uint32_t addr = stile + row * 64
                        + ((segk ^ ((row >> 1) & 3)) << 4);
                    ldm_x4(a[mi][u], addr);
                }
                const int kk = jp * KCH + ks * 32 + u * 16;
#pragma unroll
                for (int nh = 0; nh < 2; nh++) {
                    const uint32_t baddr = sb + (nh * 16 + (lane & 15)) * STRW_B
                                              + kk * 2 + (lane >> 4) * 16;
                    ldm_x4(b[u][nh], baddr);
                }
            }
            unsigned fcur = fnext;
            fnext = probe(j + 4);
            issueA(j + 3, fcur);

#pragma unroll
            for (int u = 0; u < 2; u++)
#pragma unroll
                for (int mi = 0; mi < 2; mi++)
#pragma unroll
                    for (int nh = 0; nh < 2; nh++)
#pragma unroll
                        for (int sub = 0; sub < 2; sub++)
                            mma_fp16(acc[mi][nh * 2 + sub], a[mi][u],
                                     b[u][nh][sub], b[u][nh][sub + 2]);
        }

        asm volatile("cp.async.wait_group 0;" ::: "memory");
        bar_named(barid, 128);   // all mgrp warps done reading their tiles

        // ---- partial write: mgrp-confined slice of stages 0-1 --------------
        {
            char* pw = smem + ppart;
#pragma unroll
            for (int mi = 0; mi < 2; mi++)
#pragma unroll
                for (int nf = 0; nf < 4; nf++)
                    *(float4*)(pw + (((mi * 4 + nf) * 32 + lane) << 4)) =
                        *(const float4*)acc[mi][nf];
        }
        bar_named(barid, 128);

        // ---- all-reduce slice: warp ks sums nf==ks from the other 3 -------
        float s0[2][4];
#pragma unroll
        for (int mi = 0; mi < 2; mi++)
#pragma unroll
            for (int v = 0; v < 4; v++) s0[mi][v] = acc[mi][ks][v];
#pragma unroll
        for (int s = 0; s < 4; s++) {
            if (s == ks) continue;
            const char* pr = smem + W_BYTES + (s >> 1) * STG_B + mgrp * 8192
                                  + (s & 1) * 4096;
#pragma unroll
            for (int mi = 0; mi < 2; mi++) {
                float4 v = *(const float4*)
                    (pr + (((mi * 4 + ks) * 32 + lane) << 4));
                s0[mi][0] += v.x; s0[mi][1] += v.y;
                s0[mi][2] += v.z; s0[mi][3] += v.w;
            }
        }

        // ---- epilogue: h-store first, then flag, then out stores ----------
        float hnv[2][2], cnv[2][2];
        {
            const char* xps = smem + XP_OFF + mgrp * 4608;
            __half* hw = g_h[wb];
#pragma unroll
            for (int mi = 0; mi < 2; mi++)
#pragma unroll
                for (int h = 0; h < 2; h++) {
                    float v0 = s0[mi][2 * h];
                    float v1 = s0[mi][2 * h + 1];
                    float p0 = __shfl_xor_sync(0xffffffffu, v0, 1);
                    float p1 = __shfl_xor_sync(0xffffffffu, v1, 1);
                    if (writer) {
                        int mr = mi * 16 + h * 8 + q;
                        int m = warp_m + mr;
                        int hcl = ks * 2 + hl;
                        float4 xv = *(const float4*)
                            (xps + mr * 144 + (ks * 8 + hl * 4) * 4);
                        float ig = fsig(v0 + xv.x);
                        float fg = fsig(v1 + xv.y);
                        float gg = ftanh(p0 + xv.z);
                        float og = fsig(p1 + xv.w);
                        int ci = m * 8 + hcl;
                        float cn = fg * c_s[ci] + ig * gg;
                        c_s[ci] = cn;
                        float hn = og * ftanh(cn);
                        cnv[mi][h] = cn; hnv[mi][h] = hn;
                        __stcg(&hw[(size_t)m * HH + bidx * 8 + hcl],
                               __float2half(hn));
                    }
                }
        }
        bar_named(barid, 128);   // h-stores issued; partial/stage slices free
        if (ks == 0 && lane == 0)
            red_rel(&g_flag[(size_t)t * 32 + (bidx >> 4) * 4 + mgrp]);

        // out stores off the critical path
#pragma unroll
        for (int mi = 0; mi < 2; mi++)
#pragma unroll
            for (int h = 0; h < 2; h++)
                if (writer) {
                    int m = warp_m + mi * 16 + h * 8 + q;
                    int hc = bidx * 8 + ks * 2 + hl;
                    size_t oidx = (size_t)m * HH + hc;
                    out[(size_t)t * BB * HH + oidx] = hnv[mi][h];
                    if (t == TT - 1) {
                        out[OUT_H + oidx] = hnv[mi][h];
                        out[OUT_H + (size_t)BB * HH + oidx] = cnv[mi][h];
                    }
                }

        rb = wb;
    }
}

// ============================================================================
extern "C" void kernel_launch(void* const* d_in, const int* in_sizes, int n_in,
                              void* d_out, int out_size) {
    const float* inputs = (const float*)d_in[0];
    const float* h0     = (const float*)d_in[1];
    const float* c0     = (const float*)d_in[2];
    const float* W_ih   = (const float*)d_in[3];
    const float* W_hh   = (const float*)d_in[4];
    const float* b_ih   = (const float*)d_in[5];
    const float* b_hh   = (const float*)d_in[6];
    float* out = (float*)d_out;

    cudaFuncSetAttribute(lstm_persistent,
                         cudaFuncAttributeMaxDynamicSharedMemorySize, SMEM_TOTAL);
    cudaFuncSetAttribute(xproj16_kernel,
                         cudaFuncAttributeMaxDynamicSharedMemorySize, XSMEM);

    init_state<<<(BB * HH + 255) / 256, 256>>>(h0);
    wsplit_kernel<<<(int)(((size_t)G4 * HH + 255) / 256), 256>>>(W_hh);
    conv_x16<<<(int)(((size_t)TT * BB * II + 255) / 256), 256>>>(inputs);
    conv_wih<<<(G4 * II + 255) / 256, 256>>>(W_ih, b_ih, b_hh);

    dim3 xgrid(G4 / 64, (TT * BB) / 128);
    xproj16_kernel<<<xgrid, 256, XSMEM>>>();

    lstm_persistent<<<GRIDN, NTHR, SMEM_TOTAL>>>(out, c0);
}